// round 1
// baseline (speedup 1.0000x reference)
#include <cuda_runtime.h>
#include <math.h>

#define BB 4
#define NN 4096
#define DD 64
#define KK 16

// scratch (device globals: allocation-free per harness rules)
__device__ float g_qkv[BB * NN * 192];   // point-major: [b][n][192]
__device__ int   g_idx[BB * NN * KK];

// ---------------------------------------------------------------------------
// Kernel 1: qkv = w_qkv @ points, stored point-major (b, n, 192)
// ---------------------------------------------------------------------------
__global__ void qkv_kernel(const float* __restrict__ points,
                           const float* __restrict__ w_qkv) {
    extern __shared__ float sw[];  // 192*64 floats
    int t = threadIdx.x;  // 128 threads
    for (int i = t; i < 192 * 64; i += 128) sw[i] = w_qkv[i];
    __syncthreads();
    int b = blockIdx.x >> 5;                 // 32 tiles of 128 per batch
    int n = ((blockIdx.x & 31) << 7) + t;

    float4 p4[16];
    const float* pb = points + (size_t)b * DD * NN + n;
#pragma unroll
    for (int d4 = 0; d4 < 16; ++d4) {
        p4[d4].x = pb[(size_t)(4 * d4 + 0) * NN];
        p4[d4].y = pb[(size_t)(4 * d4 + 1) * NN];
        p4[d4].z = pb[(size_t)(4 * d4 + 2) * NN];
        p4[d4].w = pb[(size_t)(4 * d4 + 3) * NN];
    }
    float* outp = g_qkv + ((size_t)(b * NN + n)) * 192;
    for (int o = 0; o < 192; ++o) {
        float acc = 0.f;
        const float4* w4 = (const float4*)(sw + o * 64);
#pragma unroll
        for (int d4 = 0; d4 < 16; ++d4) {
            float4 w = w4[d4];
            acc = fmaf(w.x, p4[d4].x, acc);
            acc = fmaf(w.y, p4[d4].y, acc);
            acc = fmaf(w.z, p4[d4].z, acc);
            acc = fmaf(w.w, p4[d4].w, acc);
        }
        outp[o] = acc;
    }
}

// ---------------------------------------------------------------------------
// Kernel 2: KNN (top-16 smallest d2, d2 = sq[n]+sq[m]-2*dot, ties -> lower idx)
// 256 threads = 64 queries x 4 candidate-partitions, then merge.
// ---------------------------------------------------------------------------
__device__ __forceinline__ void topk_insert(float d2, int m, float bd[16], int bi[16]) {
    bd[15] = d2; bi[15] = m;
#pragma unroll
    for (int i = 15; i > 0; --i) {
        if (bd[i] < bd[i - 1]) {
            float td = bd[i]; bd[i] = bd[i - 1]; bd[i - 1] = td;
            int ti = bi[i]; bi[i] = bi[i - 1]; bi[i - 1] = ti;
        }
    }
}

__global__ void knn_kernel(const float* __restrict__ xyz) {
    extern __shared__ float sm[];
    float* cx = sm;
    float* cy = cx + NN;
    float* cz = cy + NN;
    float* csq = cz + NN;
    float* md = csq + NN;               // 256*16 floats
    int* mi = (int*)(md + 256 * 16);    // 256*16 ints

    int t = threadIdx.x;               // 256
    int b = blockIdx.x >> 6;           // 64 query-tiles per batch
    int tile = blockIdx.x & 63;
    const float* xb = xyz + (size_t)b * 3 * NN;

    for (int m = t; m < NN; m += 256) {
        float x = xb[m], y = xb[NN + m], z = xb[2 * NN + m];
        cx[m] = x; cy[m] = y; cz[m] = z;
        csq[m] = x * x + y * y + z * z;
    }
    __syncthreads();

    int q = tile * 64 + (t >> 2);
    int p = t & 3;
    float qx = cx[q], qy = cy[q], qz = cz[q];
    float sqq = csq[q];

    float bd[16]; int bi[16];
#pragma unroll
    for (int i = 0; i < 16; ++i) { bd[i] = 3.4e38f; bi[i] = -1; }

    int m0 = p * 1024;
    for (int m = m0; m < m0 + 1024; ++m) {
        float dot = fmaf(qx, cx[m], fmaf(qy, cy[m], qz * cz[m]));
        float d2 = fmaf(-2.f, dot, sqq + csq[m]);
        if (d2 < bd[15]) topk_insert(d2, m, bd, bi);
    }
#pragma unroll
    for (int i = 0; i < 16; ++i) { md[t * 16 + i] = bd[i]; mi[t * 16 + i] = bi[i]; }
    __syncthreads();

    if (p == 0) {
        for (int src = 1; src < 4; ++src) {
            int base = (t + src) * 16;
            for (int e = 0; e < 16; ++e) {
                float d2 = md[base + e];
                if (d2 >= bd[15]) break;   // src list sorted ascending
                topk_insert(d2, mi[base + e], bd, bi);
            }
        }
        int* op = g_idx + ((size_t)(b * NN + q)) * KK;
#pragma unroll
        for (int i = 0; i < 16; ++i) op[i] = bi[i];
    }
}

// ---------------------------------------------------------------------------
// Kernel 3: fused gather + pos-MLP + att-MLP + softmax + aggregation.
// 512 threads, 8 queries/block, all weights in SMEM.
// ---------------------------------------------------------------------------
__global__ void __launch_bounds__(512, 1)
fused_kernel(const float* __restrict__ xyz,
             const float* __restrict__ w_pos1, const float* __restrict__ b_pos1,
             const float* __restrict__ w_pos2, const float* __restrict__ b_pos2,
             const float* __restrict__ w_att1, const float* __restrict__ b_att1,
             const float* __restrict__ w_att2, const float* __restrict__ b_att2,
             float* __restrict__ out) {
    extern __shared__ float sm[];
    float* sw1  = sm;               // w_att1 [256][64]   16384
    float* sw2  = sw1 + 16384;      // w_att2 [64][256]   16384
    float* swp2 = sw2 + 16384;      // w_pos2 [64][64]     4096
    float* swp1 = swp2 + 4096;      // w_pos1 [64][3]       192
    float* sb1  = swp1 + 192;       // b_att1               256
    float* sb2  = sb1 + 256;        // b_att2                64
    float* sbp1 = sb2 + 64;         // b_pos1                64
    float* sbp2 = sbp1 + 64;        // b_pos2                64
    float* xb   = sbp2 + 64;        // x   [16][68]
    float* vb   = xb + 16 * 68;     // v   [16][68]
    float* ph   = vb + 16 * 68;     // posh[16][68]
    float* hb   = ph + 16 * 68;     // h   [16][260]
    float* sb_s = hb + 16 * 260;    // sim [16][68]
    float* qb   = sb_s + 16 * 68;   // q   [64]
    float* gx   = qb + 64;          // gxyz [3][16]
    float* agg  = gx + 48;          // agg [8][64]
    int*   jn   = (int*)(agg + 512);// idx [16]

    int t = threadIdx.x;
    for (int i = t; i < 16384; i += 512) sw1[i] = w_att1[i];
    for (int i = t; i < 16384; i += 512) sw2[i] = w_att2[i];
    for (int i = t; i < 4096; i += 512) swp2[i] = w_pos2[i];
    if (t < 192) swp1[t] = w_pos1[t];
    if (t < 256) sb1[t] = b_att1[t];
    if (t < 64) { sb2[t] = b_att2[t]; sbp1[t] = b_pos1[t]; sbp2[t] = b_pos2[t]; }

    int b = blockIdx.x >> 9;          // 512 tiles per batch
    int n0 = (blockIdx.x & 511) << 3; // 8 queries per block
    __syncthreads();

    for (int qq = 0; qq < 8; ++qq) {
        int n = n0 + qq;
        // --- A: load idx + q ---
        if (t < 16) jn[t] = g_idx[((size_t)(b * NN + n)) * KK + t];
        if (t >= 64 && t < 128) qb[t - 64] = g_qkv[((size_t)(b * NN + n)) * 192 + (t - 64)];
        __syncthreads();
        // --- B: gather k/v, grouped xyz ---
#pragma unroll
        for (int i = 0; i < 2; ++i) {
            int e = t + 512 * i;
            int k = e >> 6, d = e & 63;
            int j = jn[k];
            const float* base = g_qkv + ((size_t)(b * NN + j)) * 192;
            xb[k * 68 + d] = qb[d] - base[64 + d];   // q - k_gathered
            vb[k * 68 + d] = base[128 + d];          // v_gathered
        }
        if (t < 48) {
            int c = t >> 4, k = t & 15;
            const float* xp = xyz + (size_t)b * 3 * NN + (size_t)c * NN;
            gx[c * 16 + k] = xp[n] - xp[jn[k]];
        }
        __syncthreads();
        // --- C: pos hidden = relu(w_pos1 @ gxyz + b_pos1) ---
#pragma unroll
        for (int i = 0; i < 2; ++i) {
            int k = t & 15;
            int h = (t >> 4) + 32 * i;
            float v = fmaf(swp1[h * 3 + 0], gx[k], sbp1[h]);
            v = fmaf(swp1[h * 3 + 1], gx[16 + k], v);
            v = fmaf(swp1[h * 3 + 2], gx[32 + k], v);
            ph[k * 68 + h] = fmaxf(v, 0.f);
        }
        __syncthreads();
        // --- D: pos emb; x += pe, v += pe ---
        {
            int k = t & 15;
            int d0 = (t >> 4), d1 = d0 + 32;
            float a0 = sbp2[d0], a1 = sbp2[d1];
            const float4* p4 = (const float4*)(ph + k * 68);
            const float4* w0 = (const float4*)(swp2 + d0 * 64);
            const float4* w1 = (const float4*)(swp2 + d1 * 64);
#pragma unroll
            for (int h4 = 0; h4 < 16; ++h4) {
                float4 pv = p4[h4];
                float4 wa = w0[h4], wb = w1[h4];
                a0 = fmaf(wa.x, pv.x, a0); a0 = fmaf(wa.y, pv.y, a0);
                a0 = fmaf(wa.z, pv.z, a0); a0 = fmaf(wa.w, pv.w, a0);
                a1 = fmaf(wb.x, pv.x, a1); a1 = fmaf(wb.y, pv.y, a1);
                a1 = fmaf(wb.z, pv.z, a1); a1 = fmaf(wb.w, pv.w, a1);
            }
            xb[k * 68 + d0] += a0; vb[k * 68 + d0] += a0;
            xb[k * 68 + d1] += a1; vb[k * 68 + d1] += a1;
        }
        __syncthreads();
        // --- E: h = relu(w_att1 @ x + b_att1)  (256x64 GEMM, 8 acc chains) ---
        {
            int k = t & 15;
            int rb = (t >> 4);
            float acc[8];
#pragma unroll
            for (int i = 0; i < 8; ++i) acc[i] = sb1[rb + 32 * i];
            const float4* x4 = (const float4*)(xb + k * 68);
#pragma unroll
            for (int d4 = 0; d4 < 16; ++d4) {
                float4 xv = x4[d4];
#pragma unroll
                for (int i = 0; i < 8; ++i) {
                    float4 w = *(const float4*)(sw1 + (rb + 32 * i) * 64 + 4 * d4);
                    acc[i] = fmaf(w.x, xv.x, acc[i]); acc[i] = fmaf(w.y, xv.y, acc[i]);
                    acc[i] = fmaf(w.z, xv.z, acc[i]); acc[i] = fmaf(w.w, xv.w, acc[i]);
                }
            }
#pragma unroll
            for (int i = 0; i < 8; ++i) hb[k * 260 + rb + 32 * i] = fmaxf(acc[i], 0.f);
        }
        __syncthreads();
        // --- F: sim = w_att2 @ h + b_att2  (64x256 GEMM) ---
        {
            int k = t & 15;
            int d0 = t >> 4, d1 = d0 + 32;
            float a0 = sb2[d0], a1 = sb2[d1];
            const float4* h4 = (const float4*)(hb + k * 260);
            const float4* w0 = (const float4*)(sw2 + d0 * 256);
            const float4* w1 = (const float4*)(sw2 + d1 * 256);
#pragma unroll 16
            for (int r4 = 0; r4 < 64; ++r4) {
                float4 hv = h4[r4];
                float4 wa = w0[r4], wb = w1[r4];
                a0 = fmaf(wa.x, hv.x, a0); a0 = fmaf(wa.y, hv.y, a0);
                a0 = fmaf(wa.z, hv.z, a0); a0 = fmaf(wa.w, hv.w, a0);
                a1 = fmaf(wb.x, hv.x, a1); a1 = fmaf(wb.y, hv.y, a1);
                a1 = fmaf(wb.z, hv.z, a1); a1 = fmaf(wb.w, hv.w, a1);
            }
            sb_s[k * 68 + d0] = a0;
            sb_s[k * 68 + d1] = a1;
        }
        __syncthreads();
        // --- G: softmax over K + weighted sum ---
        if (t < 64) {
            int d = t;
            float mx = -3.4e38f;
#pragma unroll
            for (int k = 0; k < 16; ++k) mx = fmaxf(mx, sb_s[k * 68 + d]);
            float s = 0.f, a = 0.f;
#pragma unroll
            for (int k = 0; k < 16; ++k) {
                float e = __expf(sb_s[k * 68 + d] - mx);
                s += e;
                a = fmaf(e, vb[k * 68 + d], a);
            }
            agg[qq * 64 + d] = a / s;
        }
        __syncthreads();
    }
    // --- write out: out[b][d][n], coalesced over 8 consecutive n ---
    {
        int d = t >> 3, qq = t & 7;
        out[((size_t)(b * 64 + d)) * NN + n0 + qq] = agg[qq * 64 + d];
    }
}

// ---------------------------------------------------------------------------
extern "C" void kernel_launch(void* const* d_in, const int* in_sizes, int n_in,
                              void* d_out, int out_size) {
    (void)in_sizes; (void)n_in; (void)out_size;
    const float* xyz    = (const float*)d_in[0];
    const float* points = (const float*)d_in[1];
    const float* w_qkv  = (const float*)d_in[2];
    const float* w_pos1 = (const float*)d_in[3];
    const float* b_pos1 = (const float*)d_in[4];
    const float* w_pos2 = (const float*)d_in[5];
    const float* b_pos2 = (const float*)d_in[6];
    const float* w_att1 = (const float*)d_in[7];
    const float* b_att1 = (const float*)d_in[8];
    const float* w_att2 = (const float*)d_in[9];
    const float* b_att2 = (const float*)d_in[10];
    float* out = (float*)d_out;

    cudaFuncSetAttribute(qkv_kernel, cudaFuncAttributeMaxDynamicSharedMemorySize, 49152);
    cudaFuncSetAttribute(knn_kernel, cudaFuncAttributeMaxDynamicSharedMemorySize, 98304);
    cudaFuncSetAttribute(fused_kernel, cudaFuncAttributeMaxDynamicSharedMemorySize, 186624);

    qkv_kernel<<<BB * (NN / 128), 128, 49152>>>(points, w_qkv);
    knn_kernel<<<BB * (NN / 64), 256, 98304>>>(xyz);
    fused_kernel<<<BB * (NN / 8), 512, 186624>>>(xyz,
                                                 w_pos1, b_pos1, w_pos2, b_pos2,
                                                 w_att1, b_att1, w_att2, b_att2,
                                                 out);
}

// round 2
// speedup vs baseline: 1.3132x; 1.3132x over previous
#include <cuda_runtime.h>
#include <math.h>

#define BB 4
#define NN 4096
#define KK 16

typedef unsigned long long ull;

// scratch (device globals: allocation-free per harness rules)
__device__ float g_qkv[BB * NN * 192];            // point-major: [b][n][192]
__device__ int   g_idx[BB * NN * KK];             // [b][n][k]
__device__ float g_pe[(size_t)BB * NN * KK * 64]; // [gp][64]

// ---------------- packed f32x2 helpers ----------------
__device__ __forceinline__ ull ffma2(ull a, ull b, ull c) {
    ull d;
    asm("fma.rn.f32x2 %0, %1, %2, %3;" : "=l"(d) : "l"(a), "l"(b), "l"(c));
    return d;
}
__device__ __forceinline__ ull pack2(float lo, float hi) {
    ull r;
    asm("mov.b64 %0, {%1, %2};" : "=l"(r) : "f"(lo), "f"(hi));
    return r;
}
__device__ __forceinline__ float psum(ull v) {
    float x, y;
    asm("mov.b64 {%0, %1}, %2;" : "=f"(x), "=f"(y) : "l"(v));
    return x + y;
}

// ---------------------------------------------------------------------------
// Kernel 1: qkv = w_qkv @ points, stored point-major (b, n, 192)
// 128 threads = 128 points; 4 independent accumulator chains per o-group.
// ---------------------------------------------------------------------------
__global__ void qkv_kernel(const float* __restrict__ points,
                           const float* __restrict__ w_qkv) {
    extern __shared__ float sw[];  // 192*64 floats
    int t = threadIdx.x;
    for (int i = t; i < 192 * 64; i += 128) sw[i] = w_qkv[i];
    __syncthreads();
    int b = blockIdx.x >> 5;
    int n = ((blockIdx.x & 31) << 7) + t;

    float4 p4[16];
    const float* pb = points + (size_t)b * 64 * NN + n;
#pragma unroll
    for (int d4 = 0; d4 < 16; ++d4) {
        p4[d4].x = pb[(size_t)(4 * d4 + 0) * NN];
        p4[d4].y = pb[(size_t)(4 * d4 + 1) * NN];
        p4[d4].z = pb[(size_t)(4 * d4 + 2) * NN];
        p4[d4].w = pb[(size_t)(4 * d4 + 3) * NN];
    }
    float* outp = g_qkv + ((size_t)(b * NN + n)) * 192;
    for (int ob = 0; ob < 48; ++ob) {
        float a0 = 0.f, a1 = 0.f, a2 = 0.f, a3 = 0.f;
        const float4* w0 = (const float4*)(sw + (4 * ob + 0) * 64);
        const float4* w1 = (const float4*)(sw + (4 * ob + 1) * 64);
        const float4* w2 = (const float4*)(sw + (4 * ob + 2) * 64);
        const float4* w3 = (const float4*)(sw + (4 * ob + 3) * 64);
#pragma unroll
        for (int d4 = 0; d4 < 16; ++d4) {
            float4 pv = p4[d4];
            float4 wa = w0[d4], wb = w1[d4], wc = w2[d4], wd = w3[d4];
            a0 = fmaf(wa.x, pv.x, a0); a0 = fmaf(wa.y, pv.y, a0);
            a0 = fmaf(wa.z, pv.z, a0); a0 = fmaf(wa.w, pv.w, a0);
            a1 = fmaf(wb.x, pv.x, a1); a1 = fmaf(wb.y, pv.y, a1);
            a1 = fmaf(wb.z, pv.z, a1); a1 = fmaf(wb.w, pv.w, a1);
            a2 = fmaf(wc.x, pv.x, a2); a2 = fmaf(wc.y, pv.y, a2);
            a2 = fmaf(wc.z, pv.z, a2); a2 = fmaf(wc.w, pv.w, a2);
            a3 = fmaf(wd.x, pv.x, a3); a3 = fmaf(wd.y, pv.y, a3);
            a3 = fmaf(wd.z, pv.z, a3); a3 = fmaf(wd.w, pv.w, a3);
        }
        *(float4*)(outp + 4 * ob) = make_float4(a0, a1, a2, a3);
    }
}

// ---------------------------------------------------------------------------
// Kernel 2: KNN (top-16 smallest d2) — unchanged from R1 (verified correct).
// ---------------------------------------------------------------------------
__device__ __forceinline__ void topk_insert(float d2, int m, float bd[16], int bi[16]) {
    bd[15] = d2; bi[15] = m;
#pragma unroll
    for (int i = 15; i > 0; --i) {
        if (bd[i] < bd[i - 1]) {
            float td = bd[i]; bd[i] = bd[i - 1]; bd[i - 1] = td;
            int ti = bi[i]; bi[i] = bi[i - 1]; bi[i - 1] = ti;
        }
    }
}

__global__ void knn_kernel(const float* __restrict__ xyz) {
    extern __shared__ float sm[];
    float* cx = sm;
    float* cy = cx + NN;
    float* cz = cy + NN;
    float* csq = cz + NN;
    float* md = csq + NN;
    int* mi = (int*)(md + 256 * 16);

    int t = threadIdx.x;
    int b = blockIdx.x >> 6;
    int tile = blockIdx.x & 63;
    const float* xb = xyz + (size_t)b * 3 * NN;

    for (int m = t; m < NN; m += 256) {
        float x = xb[m], y = xb[NN + m], z = xb[2 * NN + m];
        cx[m] = x; cy[m] = y; cz[m] = z;
        csq[m] = x * x + y * y + z * z;
    }
    __syncthreads();

    int q = tile * 64 + (t >> 2);
    int p = t & 3;
    float qx = cx[q], qy = cy[q], qz = cz[q];
    float sqq = csq[q];

    float bd[16]; int bi[16];
#pragma unroll
    for (int i = 0; i < 16; ++i) { bd[i] = 3.4e38f; bi[i] = -1; }

    int m0 = p * 1024;
    for (int m = m0; m < m0 + 1024; ++m) {
        float dot = fmaf(qx, cx[m], fmaf(qy, cy[m], qz * cz[m]));
        float d2 = fmaf(-2.f, dot, sqq + csq[m]);
        if (d2 < bd[15]) topk_insert(d2, m, bd, bi);
    }
#pragma unroll
    for (int i = 0; i < 16; ++i) { md[t * 16 + i] = bd[i]; mi[t * 16 + i] = bi[i]; }
    __syncthreads();

    if (p == 0) {
        for (int src = 1; src < 4; ++src) {
            int base = (t + src) * 16;
            for (int e = 0; e < 16; ++e) {
                float d2 = md[base + e];
                if (d2 >= bd[15]) break;
                topk_insert(d2, mi[base + e], bd, bi);
            }
        }
        int* op = g_idx + ((size_t)(b * NN + q)) * KK;
#pragma unroll
        for (int i = 0; i < 16; ++i) op[i] = bi[i];
    }
}

// ---------------------------------------------------------------------------
// Kernel 3: pos-MLP → g_pe.  256 pairs/block, 256 threads, GEMM 64x256x64.
// ---------------------------------------------------------------------------
__global__ void __launch_bounds__(256, 2)
pos_kernel(const float* __restrict__ xyz,
           const float* __restrict__ w_pos1, const float* __restrict__ b_pos1,
           const float* __restrict__ w_pos2, const float* __restrict__ b_pos2) {
    extern __shared__ float sm[];
    float* swp2 = sm;                // [64][64] natural: w_pos2[o*64+h]   4096
    float* swp1 = swp2 + 4096;       // [64][3]                             192
    float* sbp1 = swp1 + 192;        // 64
    float* sbp2 = sbp1 + 64;         // 64
    float* sph  = sbp2 + 64;         // ph [64 h][256 p]                  16384

    int t = threadIdx.x;
    for (int i = t; i < 4096; i += 256) swp2[i] = w_pos2[i];
    if (t < 192) swp1[t] = w_pos1[t];
    if (t < 64) { sbp1[t] = b_pos1[t]; sbp2[t] = b_pos2[t]; }

    size_t gp0 = (size_t)blockIdx.x * 256;
    int b = (int)(gp0 >> 16);
    // layer 1: one pair per thread
    {
        size_t gp = gp0 + t;
        int n = (int)((gp >> 4) & 4095);
        int j = g_idx[gp];
        const float* xb = xyz + (size_t)b * 3 * NN;
        float gx0 = xb[n] - xb[j];
        float gx1 = xb[NN + n] - xb[NN + j];
        float gx2 = xb[2 * NN + n] - xb[2 * NN + j];
        __syncthreads();
#pragma unroll 8
        for (int h = 0; h < 64; ++h) {
            float v = fmaf(swp1[h * 3 + 0], gx0, sbp1[h]);
            v = fmaf(swp1[h * 3 + 1], gx1, v);
            v = fmaf(swp1[h * 3 + 2], gx2, v);
            sph[h * 256 + t] = fmaxf(v, 0.f);
        }
    }
    __syncthreads();

    // layer 2 GEMM: pe[64 o][256 p] = wp2[64][64] @ ph[64][256]
    int rg = t >> 5;          // 8 row groups of 8 o
    int pg = t & 31;          // 32 col groups of 8 p
    int o0 = rg * 8, p0 = pg * 8;
    float acc[8][8];
#pragma unroll
    for (int r = 0; r < 8; ++r)
#pragma unroll
        for (int c = 0; c < 8; ++c) acc[r][c] = sbp2[o0 + r];

    for (int k = 0; k < 64; k += 4) {
        float4 pa[4], pb[4];
#pragma unroll
        for (int kk = 0; kk < 4; ++kk) {
            pa[kk] = *(const float4*)(sph + (k + kk) * 256 + p0);
            pb[kk] = *(const float4*)(sph + (k + kk) * 256 + p0 + 4);
        }
#pragma unroll
        for (int r = 0; r < 8; ++r) {
            float4 w = *(const float4*)(swp2 + (o0 + r) * 64 + k);
#pragma unroll
            for (int c = 0; c < 4; ++c) {
                acc[r][c] = fmaf(w.x, ((const float*)&pa[0])[c], acc[r][c]);
                acc[r][c] = fmaf(w.y, ((const float*)&pa[1])[c], acc[r][c]);
                acc[r][c] = fmaf(w.z, ((const float*)&pa[2])[c], acc[r][c]);
                acc[r][c] = fmaf(w.w, ((const float*)&pa[3])[c], acc[r][c]);
                acc[r][c + 4] = fmaf(w.x, ((const float*)&pb[0])[c], acc[r][c + 4]);
                acc[r][c + 4] = fmaf(w.y, ((const float*)&pb[1])[c], acc[r][c + 4]);
                acc[r][c + 4] = fmaf(w.z, ((const float*)&pb[2])[c], acc[r][c + 4]);
                acc[r][c + 4] = fmaf(w.w, ((const float*)&pb[3])[c], acc[r][c + 4]);
            }
        }
    }
#pragma unroll
    for (int i = 0; i < 8; ++i) {
        float* dst = g_pe + (gp0 + p0 + i) * 64 + o0;
        *(float4*)(dst)     = make_float4(acc[0][i], acc[1][i], acc[2][i], acc[3][i]);
        *(float4*)(dst + 4) = make_float4(acc[4][i], acc[5][i], acc[6][i], acc[7][i]);
    }
}

// ---------------------------------------------------------------------------
// Kernel 4: fused gather + att-MLP + softmax + aggregation.
// 512 threads, 4 queries (64 cols)/block. f32x2 packed GEMMs (k-paired lanes).
// ---------------------------------------------------------------------------
__global__ void __launch_bounds__(512, 1)
fused_kernel(const float* __restrict__ w_att1, const float* __restrict__ b_att1,
             const float* __restrict__ w_att2, const float* __restrict__ b_att2,
             float* __restrict__ out) {
    extern __shared__ float sm[];
    float* sw1 = sm;               // w_att1 [256][64]  16384
    float* sw2 = sw1 + 16384;      // w_att2 [64][256]  16384
    float* sh  = sw2 + 16384;      // h [256][64]       16384
    float* sx  = sh + 16384;       // x [64][64] (sim aliases after E) 4096
    float* sv  = sx + 4096;        // v [64][64]        4096
    float* sb1 = sv + 4096;        // 256
    float* sb2 = sb1 + 256;        // 64
    float* sq  = sb2 + 64;         // q [4][64]         256
    int*   sj  = (int*)(sq + 256); // 64

    int t = threadIdx.x;
    for (int i = t; i < 16384; i += 512) sw1[i] = w_att1[i];
    for (int i = t; i < 16384; i += 512) sw2[i] = w_att2[i];
    if (t < 256) sb1[t] = b_att1[t];
    if (t < 64) sb2[t] = b_att2[t];

    int b = blockIdx.x >> 10;
    int n0 = (blockIdx.x & 1023) << 2;

    if (t < 64) sj[t] = g_idx[((size_t)(b * NN + n0)) * KK + t];
    if (t >= 64 && t < 320) {
        int i = t - 64;
        sq[i] = g_qkv[((size_t)(b * NN + n0 + (i >> 6))) * 192 + (i & 63)];
    }
    __syncthreads();

    // ---- gather: x = q - k_gathered + pe ; v = v_gathered + pe ----
    {
        int c = t & 63;
        int d0 = (t >> 6) * 8;
        int j = sj[c];
        int qq = c >> 4;
        const float* base = g_qkv + ((size_t)(b * NN + j)) * 192;
        const float* pep = g_pe + ((size_t)b * 65536 + (size_t)n0 * 16 + c) * 64;
#pragma unroll
        for (int i = 0; i < 2; ++i) {
            int d = d0 + 4 * i;
            float4 kk = *(const float4*)(base + 64 + d);
            float4 vv = *(const float4*)(base + 128 + d);
            float4 pe = *(const float4*)(pep + d);
            const float* qv = sq + qq * 64 + d;
            sx[(d + 0) * 64 + c] = qv[0] - kk.x + pe.x;
            sx[(d + 1) * 64 + c] = qv[1] - kk.y + pe.y;
            sx[(d + 2) * 64 + c] = qv[2] - kk.z + pe.z;
            sx[(d + 3) * 64 + c] = qv[3] - kk.w + pe.w;
            sv[(d + 0) * 64 + c] = vv.x + pe.x;
            sv[(d + 1) * 64 + c] = vv.y + pe.y;
            sv[(d + 2) * 64 + c] = vv.z + pe.z;
            sv[(d + 3) * 64 + c] = vv.w + pe.w;
        }
    }
    __syncthreads();

    // ---- E: h[256][64] = relu(w1 @ x + b1), f32x2 k-paired ----
    {
        int rg = t >> 4, cg = t & 15;
        int r0 = rg * 8, c0 = cg * 4;
        ull acc[8][4];
#pragma unroll
        for (int r = 0; r < 8; ++r) {
            ull init = pack2(sb1[r0 + r], 0.f);
#pragma unroll
            for (int c = 0; c < 4; ++c) acc[r][c] = init;
        }
#pragma unroll 2
        for (int k = 0; k < 64; k += 4) {
            float4 x0 = *(const float4*)(sx + (k + 0) * 64 + c0);
            float4 x1 = *(const float4*)(sx + (k + 1) * 64 + c0);
            float4 x2 = *(const float4*)(sx + (k + 2) * 64 + c0);
            float4 x3 = *(const float4*)(sx + (k + 3) * 64 + c0);
            ull bx0[4], bx1[4];
            bx0[0] = pack2(x0.x, x1.x); bx0[1] = pack2(x0.y, x1.y);
            bx0[2] = pack2(x0.z, x1.z); bx0[3] = pack2(x0.w, x1.w);
            bx1[0] = pack2(x2.x, x3.x); bx1[1] = pack2(x2.y, x3.y);
            bx1[2] = pack2(x2.z, x3.z); bx1[3] = pack2(x2.w, x3.w);
#pragma unroll
            for (int r = 0; r < 8; ++r) {
                longlong2 wv = *(const longlong2*)(sw1 + (r0 + r) * 64 + k);
#pragma unroll
                for (int c = 0; c < 4; ++c) {
                    acc[r][c] = ffma2((ull)wv.x, bx0[c], acc[r][c]);
                    acc[r][c] = ffma2((ull)wv.y, bx1[c], acc[r][c]);
                }
            }
        }
#pragma unroll
        for (int r = 0; r < 8; ++r)
#pragma unroll
            for (int c = 0; c < 4; ++c)
                sh[(r0 + r) * 64 + c0 + c] = fmaxf(psum(acc[r][c]), 0.f);
    }
    __syncthreads();

    // ---- F: sim[64][64] = w2 @ h + b2 (sim aliases sx), f32x2 k-paired ----
    if (t < 256) {
        int rg = t >> 4, cg = t & 15;
        int r0 = rg * 4, c0 = cg * 4;
        ull acc[4][4];
#pragma unroll
        for (int r = 0; r < 4; ++r) {
            ull init = pack2(sb2[r0 + r], 0.f);
#pragma unroll
            for (int c = 0; c < 4; ++c) acc[r][c] = init;
        }
#pragma unroll 2
        for (int k = 0; k < 256; k += 4) {
            float4 h0 = *(const float4*)(sh + (k + 0) * 64 + c0);
            float4 h1 = *(const float4*)(sh + (k + 1) * 64 + c0);
            float4 h2 = *(const float4*)(sh + (k + 2) * 64 + c0);
            float4 h3 = *(const float4*)(sh + (k + 3) * 64 + c0);
            ull bx0[4], bx1[4];
            bx0[0] = pack2(h0.x, h1.x); bx0[1] = pack2(h0.y, h1.y);
            bx0[2] = pack2(h0.z, h1.z); bx0[3] = pack2(h0.w, h1.w);
            bx1[0] = pack2(h2.x, h3.x); bx1[1] = pack2(h2.y, h3.y);
            bx1[2] = pack2(h2.z, h3.z); bx1[3] = pack2(h2.w, h3.w);
#pragma unroll
            for (int r = 0; r < 4; ++r) {
                longlong2 wv = *(const longlong2*)(sw2 + (r0 + r) * 256 + k);
#pragma unroll
                for (int c = 0; c < 4; ++c) {
                    acc[r][c] = ffma2((ull)wv.x, bx0[c], acc[r][c]);
                    acc[r][c] = ffma2((ull)wv.y, bx1[c], acc[r][c]);
                }
            }
        }
#pragma unroll
        for (int r = 0; r < 4; ++r)
#pragma unroll
            for (int c = 0; c < 4; ++c)
                sx[(r0 + r) * 64 + c0 + c] = psum(acc[r][c]);
    }
    __syncthreads();

    // ---- softmax over K + weighted sum ----
    if (t < 256) {
        int d = t >> 2, qq = t & 3;
        const float* sp = sx + d * 64 + qq * 16;
        const float* vp = sv + d * 64 + qq * 16;
        float mx = -3.4e38f;
#pragma unroll
        for (int k = 0; k < 16; ++k) mx = fmaxf(mx, sp[k]);
        float s = 0.f, a = 0.f;
#pragma unroll
        for (int k = 0; k < 16; ++k) {
            float e = __expf(sp[k] - mx);
            s += e;
            a = fmaf(e, vp[k], a);
        }
        out[((size_t)(b * 64 + d)) * NN + n0 + qq] = a / s;
    }
}

// ---------------------------------------------------------------------------
extern "C" void kernel_launch(void* const* d_in, const int* in_sizes, int n_in,
                              void* d_out, int out_size) {
    (void)in_sizes; (void)n_in; (void)out_size;
    const float* xyz    = (const float*)d_in[0];
    const float* points = (const float*)d_in[1];
    const float* w_qkv  = (const float*)d_in[2];
    const float* w_pos1 = (const float*)d_in[3];
    const float* b_pos1 = (const float*)d_in[4];
    const float* w_pos2 = (const float*)d_in[5];
    const float* b_pos2 = (const float*)d_in[6];
    const float* w_att1 = (const float*)d_in[7];
    const float* b_att1 = (const float*)d_in[8];
    const float* w_att2 = (const float*)d_in[9];
    const float* b_att2 = (const float*)d_in[10];
    float* out = (float*)d_out;

    cudaFuncSetAttribute(qkv_kernel, cudaFuncAttributeMaxDynamicSharedMemorySize, 49152);
    cudaFuncSetAttribute(knn_kernel, cudaFuncAttributeMaxDynamicSharedMemorySize, 98304);
    cudaFuncSetAttribute(pos_kernel, cudaFuncAttributeMaxDynamicSharedMemorySize, 83200);
    cudaFuncSetAttribute(fused_kernel, cudaFuncAttributeMaxDynamicSharedMemorySize, 231936);

    qkv_kernel<<<BB * (NN / 128), 128, 49152>>>(points, w_qkv);
    knn_kernel<<<BB * (NN / 64), 256, 98304>>>(xyz);
    pos_kernel<<<BB * NN * KK / 256, 256, 83200>>>(xyz, w_pos1, b_pos1, w_pos2, b_pos2);
    fused_kernel<<<BB * (NN / 4), 512, 231936>>>(w_att1, b_att1, w_att2, b_att2, out);
}

// round 3
// speedup vs baseline: 1.5059x; 1.1467x over previous
#include <cuda_runtime.h>
#include <math.h>

#define BB 4
#define NN 4096
#define KK 16

typedef unsigned long long ull;

// scratch (device globals: allocation-free per harness rules)
__device__ float g_qkv[BB * NN * 192];            // point-major: [b][n][192]
__device__ int   g_idx[BB * NN * KK];             // [b][n][k]
__device__ float g_pe[(size_t)BB * NN * KK * 64]; // [gp][64]

// ---------------- packed f32x2 helpers ----------------
__device__ __forceinline__ ull ffma2(ull a, ull b, ull c) {
    ull d;
    asm("fma.rn.f32x2 %0, %1, %2, %3;" : "=l"(d) : "l"(a), "l"(b), "l"(c));
    return d;
}
__device__ __forceinline__ ull pack2(float lo, float hi) {
    ull r;
    asm("mov.b64 %0, {%1, %2};" : "=l"(r) : "f"(lo), "f"(hi));
    return r;
}
__device__ __forceinline__ float psum(ull v) {
    float x, y;
    asm("mov.b64 {%0, %1}, %2;" : "=f"(x), "=f"(y) : "l"(v));
    return x + y;
}

// byte-offset swizzle within a 512B row (keeps low 4 bits)
#define SWZ(L) ((L) ^ (((L) >> 3) & 0x70))

// ---------------------------------------------------------------------------
// Kernel 1: qkv = w_qkv @ points, point-major out. 256 thr: o-dim split x2.
// ---------------------------------------------------------------------------
__global__ void qkv_kernel(const float* __restrict__ points,
                           const float* __restrict__ w_qkv) {
    extern __shared__ float sw[];  // 192*64 floats
    int t = threadIdx.x;  // 256
    {
        const float4* a = (const float4*)w_qkv;
        float4* d = (float4*)sw;
        for (int i = t; i < 3072; i += 256) d[i] = a[i];
    }
    __syncthreads();
    int b = blockIdx.x >> 5;
    int n = ((blockIdx.x & 31) << 7) + (t & 127);
    int oh = t >> 7;

    float4 p4[16];
    const float* pb = points + (size_t)b * 64 * NN + n;
#pragma unroll
    for (int d4 = 0; d4 < 16; ++d4) {
        p4[d4].x = pb[(size_t)(4 * d4 + 0) * NN];
        p4[d4].y = pb[(size_t)(4 * d4 + 1) * NN];
        p4[d4].z = pb[(size_t)(4 * d4 + 2) * NN];
        p4[d4].w = pb[(size_t)(4 * d4 + 3) * NN];
    }
    float* outp = g_qkv + ((size_t)(b * NN + n)) * 192 + oh * 96;
    const float* swh = sw + oh * 96 * 64;
    for (int ob = 0; ob < 24; ++ob) {
        float a0 = 0.f, a1 = 0.f, a2 = 0.f, a3 = 0.f;
        const float4* w0 = (const float4*)(swh + (4 * ob + 0) * 64);
        const float4* w1 = (const float4*)(swh + (4 * ob + 1) * 64);
        const float4* w2 = (const float4*)(swh + (4 * ob + 2) * 64);
        const float4* w3 = (const float4*)(swh + (4 * ob + 3) * 64);
#pragma unroll
        for (int d4 = 0; d4 < 16; ++d4) {
            float4 pv = p4[d4];
            float4 wa = w0[d4], wb = w1[d4], wc = w2[d4], wd = w3[d4];
            a0 = fmaf(wa.x, pv.x, a0); a0 = fmaf(wa.y, pv.y, a0);
            a0 = fmaf(wa.z, pv.z, a0); a0 = fmaf(wa.w, pv.w, a0);
            a1 = fmaf(wb.x, pv.x, a1); a1 = fmaf(wb.y, pv.y, a1);
            a1 = fmaf(wb.z, pv.z, a1); a1 = fmaf(wb.w, pv.w, a1);
            a2 = fmaf(wc.x, pv.x, a2); a2 = fmaf(wc.y, pv.y, a2);
            a2 = fmaf(wc.z, pv.z, a2); a2 = fmaf(wc.w, pv.w, a2);
            a3 = fmaf(wd.x, pv.x, a3); a3 = fmaf(wd.y, pv.y, a3);
            a3 = fmaf(wd.z, pv.z, a3); a3 = fmaf(wd.w, pv.w, a3);
        }
        *(float4*)(outp + 4 * ob) = make_float4(a0, a1, a2, a3);
    }
}

// ---------------------------------------------------------------------------
// Kernel 2: KNN (top-16 smallest d2) — verified correct, keep.
// ---------------------------------------------------------------------------
__device__ __forceinline__ void topk_insert(float d2, int m, float bd[16], int bi[16]) {
    bd[15] = d2; bi[15] = m;
#pragma unroll
    for (int i = 15; i > 0; --i) {
        if (bd[i] < bd[i - 1]) {
            float td = bd[i]; bd[i] = bd[i - 1]; bd[i - 1] = td;
            int ti = bi[i]; bi[i] = bi[i - 1]; bi[i - 1] = ti;
        }
    }
}

__global__ void knn_kernel(const float* __restrict__ xyz) {
    extern __shared__ float sm[];
    float* cx = sm;
    float* cy = cx + NN;
    float* cz = cy + NN;
    float* csq = cz + NN;
    float* md = csq + NN;
    int* mi = (int*)(md + 256 * 16);

    int t = threadIdx.x;
    int b = blockIdx.x >> 6;
    int tile = blockIdx.x & 63;
    const float* xb = xyz + (size_t)b * 3 * NN;

    for (int m = t; m < NN; m += 256) {
        float x = xb[m], y = xb[NN + m], z = xb[2 * NN + m];
        cx[m] = x; cy[m] = y; cz[m] = z;
        csq[m] = x * x + y * y + z * z;
    }
    __syncthreads();

    int q = tile * 64 + (t >> 2);
    int p = t & 3;
    float qx = cx[q], qy = cy[q], qz = cz[q];
    float sqq = csq[q];

    float bd[16]; int bi[16];
#pragma unroll
    for (int i = 0; i < 16; ++i) { bd[i] = 3.4e38f; bi[i] = -1; }

    int m0 = p * 1024;
    for (int m = m0; m < m0 + 1024; ++m) {
        float dot = fmaf(qx, cx[m], fmaf(qy, cy[m], qz * cz[m]));
        float d2 = fmaf(-2.f, dot, sqq + csq[m]);
        if (d2 < bd[15]) topk_insert(d2, m, bd, bi);
    }
#pragma unroll
    for (int i = 0; i < 16; ++i) { md[t * 16 + i] = bd[i]; mi[t * 16 + i] = bi[i]; }
    __syncthreads();

    if (p == 0) {
        for (int src = 1; src < 4; ++src) {
            int base = (t + src) * 16;
            for (int e = 0; e < 16; ++e) {
                float d2 = md[base + e];
                if (d2 >= bd[15]) break;
                topk_insert(d2, mi[base + e], bd, bi);
            }
        }
        int* op = g_idx + ((size_t)(b * NN + q)) * KK;
#pragma unroll
        for (int i = 0; i < 16; ++i) op[i] = bi[i];
    }
}

// ---------------------------------------------------------------------------
// Kernel 3: pos-MLP -> g_pe (unchanged from R2).
// ---------------------------------------------------------------------------
__global__ void __launch_bounds__(256, 2)
pos_kernel(const float* __restrict__ xyz,
           const float* __restrict__ w_pos1, const float* __restrict__ b_pos1,
           const float* __restrict__ w_pos2, const float* __restrict__ b_pos2) {
    extern __shared__ float sm[];
    float* swp2 = sm;
    float* swp1 = swp2 + 4096;
    float* sbp1 = swp1 + 192;
    float* sbp2 = sbp1 + 64;
    float* sph  = sbp2 + 64;

    int t = threadIdx.x;
    for (int i = t; i < 4096; i += 256) swp2[i] = w_pos2[i];
    if (t < 192) swp1[t] = w_pos1[t];
    if (t < 64) { sbp1[t] = b_pos1[t]; sbp2[t] = b_pos2[t]; }

    size_t gp0 = (size_t)blockIdx.x * 256;
    int b = (int)(gp0 >> 16);
    {
        size_t gp = gp0 + t;
        int n = (int)((gp >> 4) & 4095);
        int j = g_idx[gp];
        const float* xb = xyz + (size_t)b * 3 * NN;
        float gx0 = xb[n] - xb[j];
        float gx1 = xb[NN + n] - xb[NN + j];
        float gx2 = xb[2 * NN + n] - xb[2 * NN + j];
        __syncthreads();
#pragma unroll 8
        for (int h = 0; h < 64; ++h) {
            float v = fmaf(swp1[h * 3 + 0], gx0, sbp1[h]);
            v = fmaf(swp1[h * 3 + 1], gx1, v);
            v = fmaf(swp1[h * 3 + 2], gx2, v);
            sph[h * 256 + t] = fmaxf(v, 0.f);
        }
    }
    __syncthreads();

    int rg = t >> 5;
    int pg = t & 31;
    int o0 = rg * 8, p0 = pg * 8;
    float acc[8][8];
#pragma unroll
    for (int r = 0; r < 8; ++r)
#pragma unroll
        for (int c = 0; c < 8; ++c) acc[r][c] = sbp2[o0 + r];

    for (int k = 0; k < 64; k += 4) {
        float4 pa[4], pb[4];
#pragma unroll
        for (int kk = 0; kk < 4; ++kk) {
            pa[kk] = *(const float4*)(sph + (k + kk) * 256 + p0);
            pb[kk] = *(const float4*)(sph + (k + kk) * 256 + p0 + 4);
        }
#pragma unroll
        for (int r = 0; r < 8; ++r) {
            float4 w = *(const float4*)(swp2 + (o0 + r) * 64 + k);
#pragma unroll
            for (int c = 0; c < 4; ++c) {
                acc[r][c] = fmaf(w.x, ((const float*)&pa[0])[c], acc[r][c]);
                acc[r][c] = fmaf(w.y, ((const float*)&pa[1])[c], acc[r][c]);
                acc[r][c] = fmaf(w.z, ((const float*)&pa[2])[c], acc[r][c]);
                acc[r][c] = fmaf(w.w, ((const float*)&pa[3])[c], acc[r][c]);
                acc[r][c + 4] = fmaf(w.x, ((const float*)&pb[0])[c], acc[r][c + 4]);
                acc[r][c + 4] = fmaf(w.y, ((const float*)&pb[1])[c], acc[r][c + 4]);
                acc[r][c + 4] = fmaf(w.z, ((const float*)&pb[2])[c], acc[r][c + 4]);
                acc[r][c + 4] = fmaf(w.w, ((const float*)&pb[3])[c], acc[r][c + 4]);
            }
        }
    }
#pragma unroll
    for (int i = 0; i < 8; ++i) {
        float* dst = g_pe + (gp0 + p0 + i) * 64 + o0;
        *(float4*)(dst)     = make_float4(acc[0][i], acc[1][i], acc[2][i], acc[3][i]);
        *(float4*)(dst + 4) = make_float4(acc[4][i], acc[5][i], acc[6][i], acc[7][i]);
    }
}

// ---------------------------------------------------------------------------
// Kernel 4: fused gather + att-MLP + softmax + aggregation.
// 256 threads, 2 tiles x 4 queries/block. k-paired FFMA2, 8x8 reg tiles,
// swizzled SMEM operand layout (no packing movs in the hot loops).
// ---------------------------------------------------------------------------
__global__ void __launch_bounds__(256, 1)
fused_kernel(const float* __restrict__ w_att1, const float* __restrict__ b_att1,
             const float* __restrict__ w_att2, const float* __restrict__ b_att2,
             float* __restrict__ out) {
    extern __shared__ float sm[];
    float* sw1 = sm;               // 16384  w_att1 [256][64]
    float* sw2 = sw1 + 16384;      // 16384  w_att2 [64][256]
    float* sh2 = sw2 + 16384;      // 16384  h, k-paired [128 kp][64 c x2]
    float* sx2 = sh2 + 16384;      // 4096   x, k-paired [32 kp][64 c x2] ; ssim alias
    float* sv  = sx2 + 4096;       // 4096   v [64 d][64 c]
    float* sb1 = sv + 4096;        // 256
    float* sb2 = sb1 + 256;        // 64
    float* sq  = sb2 + 64;         // 256
    int*   sj  = (int*)(sq + 256); // 64

    int t = threadIdx.x;
    {
        const float4* a1 = (const float4*)w_att1;
        const float4* a2 = (const float4*)w_att2;
        float4* d1 = (float4*)sw1;
        float4* d2 = (float4*)sw2;
        for (int i = t; i < 4096; i += 256) d1[i] = a1[i];
        for (int i = t; i < 4096; i += 256) d2[i] = a2[i];
    }
    sb1[t] = b_att1[t];
    if (t < 64) sb2[t] = b_att2[t];

    int b = blockIdx.x >> 9;
    int nb = (blockIdx.x & 511) << 3;

    for (int tile = 0; tile < 2; ++tile) {
        int n0 = nb + tile * 4;
        __syncthreads();
        if (t < 64) sj[t] = g_idx[((size_t)(b * NN + n0)) * KK + t];
        sq[t] = g_qkv[((size_t)(b * NN + n0 + (t >> 6))) * 192 + (t & 63)];
        __syncthreads();

        // ---- gather: x = q - k + pe (k-paired, swizzled); v = v + pe ----
        {
            int c = t & 63;
            int d0 = (t >> 6) * 16;
            int j = sj[c];
            const float* qv = sq + (c >> 4) * 64;
            const float* base = g_qkv + ((size_t)(b * NN + j)) * 192;
            const float* pep = g_pe + ((size_t)b * 65536 + (size_t)n0 * 16 + c) * 64;
            int cb = SWZ(c * 8) >> 2;  // float index of this c's 8B slot in a row
#pragma unroll
            for (int i = 0; i < 4; ++i) {
                int d = d0 + 4 * i;
                float4 kk = *(const float4*)(base + 64 + d);
                float4 vv = *(const float4*)(base + 128 + d);
                float4 pe = *(const float4*)(pep + d);
                float x0 = qv[d + 0] - kk.x + pe.x;
                float x1 = qv[d + 1] - kk.y + pe.y;
                float x2 = qv[d + 2] - kk.z + pe.z;
                float x3 = qv[d + 3] - kk.w + pe.w;
                *(ull*)(sx2 + (d >> 1) * 128 + cb)       = pack2(x0, x1);
                *(ull*)(sx2 + ((d >> 1) + 1) * 128 + cb) = pack2(x2, x3);
                sv[(d + 0) * 64 + c] = vv.x + pe.x;
                sv[(d + 1) * 64 + c] = vv.y + pe.y;
                sv[(d + 2) * 64 + c] = vv.z + pe.z;
                sv[(d + 3) * 64 + c] = vv.w + pe.w;
            }
        }
        __syncthreads();

        // ---- E: h[256][64] = relu(w1 @ x + b1) ----
        {
            int rg = t >> 3, cg = t & 7;
            int r0 = rg * 8;
            int co[4];
#pragma unroll
            for (int i = 0; i < 4; ++i) {
                int L = cg * 64 + i * 16;
                co[i] = SWZ(L) >> 2;
            }
            ull acc[8][8];
#pragma unroll
            for (int r = 0; r < 8; ++r) {
                ull ini = pack2(sb1[r0 + r], 0.f);
#pragma unroll
                for (int c = 0; c < 8; ++c) acc[r][c] = ini;
            }
#pragma unroll 1
            for (int kp2 = 0; kp2 < 16; ++kp2) {
                const float* row0 = sx2 + (2 * kp2) * 128;
                const float* row1 = row0 + 128;
                ulonglong2 b0[4], b1[4];
#pragma unroll
                for (int i = 0; i < 4; ++i) {
                    b0[i] = *(const ulonglong2*)(row0 + co[i]);
                    b1[i] = *(const ulonglong2*)(row1 + co[i]);
                }
#pragma unroll
                for (int r = 0; r < 8; ++r) {
                    ulonglong2 wv = *(const ulonglong2*)(sw1 + (r0 + r) * 64 + kp2 * 4);
#pragma unroll
                    for (int i = 0; i < 4; ++i) {
                        acc[r][2 * i]     = ffma2(wv.x, b0[i].x, acc[r][2 * i]);
                        acc[r][2 * i + 1] = ffma2(wv.x, b0[i].y, acc[r][2 * i + 1]);
                        acc[r][2 * i]     = ffma2(wv.y, b1[i].x, acc[r][2 * i]);
                        acc[r][2 * i + 1] = ffma2(wv.y, b1[i].y, acc[r][2 * i + 1]);
                    }
                }
            }
            // epilogue: relu(lo+hi), pack row-pairs, store to sh2 (k-paired)
#pragma unroll
            for (int rp = 0; rp < 4; ++rp) {
                float* dst = sh2 + (rg * 4 + rp) * 128;
#pragma unroll
                for (int i = 0; i < 4; ++i) {
                    float h0a = fmaxf(psum(acc[2 * rp][2 * i]), 0.f);
                    float h1a = fmaxf(psum(acc[2 * rp + 1][2 * i]), 0.f);
                    float h0b = fmaxf(psum(acc[2 * rp][2 * i + 1]), 0.f);
                    float h1b = fmaxf(psum(acc[2 * rp + 1][2 * i + 1]), 0.f);
                    *(ull*)(dst + co[i])     = pack2(h0a, h1a);
                    *(ull*)(dst + co[i] + 2) = pack2(h0b, h1b);
                }
            }
        }
        __syncthreads();

        // ---- F: sim[64][64] = w2 @ h + b2, K split in halves over threads ----
        {
            int half = t >> 7;
            int tt = t & 127;
            int rt_ = tt >> 3;   // 0..15
            int ct_ = tt & 7;    // 0..7
            int r0 = rt_ * 4;
            int co[4];
#pragma unroll
            for (int i = 0; i < 4; ++i) {
                int L = ct_ * 64 + i * 16;
                co[i] = SWZ(L) >> 2;
            }
            ull acc[4][8];
#pragma unroll
            for (int r = 0; r < 4; ++r)
#pragma unroll
                for (int c = 0; c < 8; ++c) acc[r][c] = 0ULL;

            const float* swr = sw2 + half * 128;       // k offset within w2 rows
            const float* shb = sh2 + half * 64 * 128;  // kp rows for this half
#pragma unroll 1
            for (int kp2 = 0; kp2 < 32; ++kp2) {
                const float* row0 = shb + (2 * kp2) * 128;
                const float* row1 = row0 + 128;
                ulonglong2 b0[4], b1[4];
#pragma unroll
                for (int i = 0; i < 4; ++i) {
                    b0[i] = *(const ulonglong2*)(row0 + co[i]);
                    b1[i] = *(const ulonglong2*)(row1 + co[i]);
                }
#pragma unroll
                for (int r = 0; r < 4; ++r) {
                    ulonglong2 wv = *(const ulonglong2*)(swr + (r0 + r) * 256 + kp2 * 4);
#pragma unroll
                    for (int i = 0; i < 4; ++i) {
                        acc[r][2 * i]     = ffma2(wv.x, b0[i].x, acc[r][2 * i]);
                        acc[r][2 * i + 1] = ffma2(wv.x, b0[i].y, acc[r][2 * i + 1]);
                        acc[r][2 * i]     = ffma2(wv.y, b1[i].x, acc[r][2 * i]);
                        acc[r][2 * i + 1] = ffma2(wv.y, b1[i].y, acc[r][2 * i + 1]);
                    }
                }
            }
            float* ssim = sx2;  // alias (x consumed)
            if (half == 0) {
#pragma unroll
                for (int r = 0; r < 4; ++r) {
                    float bias = sb2[r0 + r];
#pragma unroll
                    for (int c = 0; c < 8; ++c)
                        ssim[(r0 + r) * 64 + ct_ * 8 + c] = bias + psum(acc[r][c]);
                }
            }
            __syncthreads();
            if (half == 1) {
#pragma unroll
                for (int r = 0; r < 4; ++r)
#pragma unroll
                    for (int c = 0; c < 8; ++c)
                        ssim[(r0 + r) * 64 + ct_ * 8 + c] += psum(acc[r][c]);
            }
        }
        __syncthreads();

        // ---- softmax over K + weighted sum ----
        {
            int d = t >> 2, qq = t & 3;
            const float* sp = sx2 + d * 64 + qq * 16;
            const float* vp = sv + d * 64 + qq * 16;
            float mx = -3.4e38f;
#pragma unroll
            for (int k = 0; k < 16; ++k) mx = fmaxf(mx, sp[k]);
            float s = 0.f, a = 0.f;
#pragma unroll
            for (int k = 0; k < 16; ++k) {
                float e = __expf(sp[k] - mx);
                s += e;
                a = fmaf(e, vp[k], a);
            }
            out[((size_t)(b * 64 + d)) * NN + n0 + qq] = a / s;
        }
    }
}

// ---------------------------------------------------------------------------
extern "C" void kernel_launch(void* const* d_in, const int* in_sizes, int n_in,
                              void* d_out, int out_size) {
    (void)in_sizes; (void)n_in; (void)out_size;
    const float* xyz    = (const float*)d_in[0];
    const float* points = (const float*)d_in[1];
    const float* w_qkv  = (const float*)d_in[2];
    const float* w_pos1 = (const float*)d_in[3];
    const float* b_pos1 = (const float*)d_in[4];
    const float* w_pos2 = (const float*)d_in[5];
    const float* b_pos2 = (const float*)d_in[6];
    const float* w_att1 = (const float*)d_in[7];
    const float* b_att1 = (const float*)d_in[8];
    const float* w_att2 = (const float*)d_in[9];
    const float* b_att2 = (const float*)d_in[10];
    float* out = (float*)d_out;

    cudaFuncSetAttribute(qkv_kernel, cudaFuncAttributeMaxDynamicSharedMemorySize, 49152);
    cudaFuncSetAttribute(knn_kernel, cudaFuncAttributeMaxDynamicSharedMemorySize, 98304);
    cudaFuncSetAttribute(pos_kernel, cudaFuncAttributeMaxDynamicSharedMemorySize, 83200);
    cudaFuncSetAttribute(fused_kernel, cudaFuncAttributeMaxDynamicSharedMemorySize, 231936);

    qkv_kernel<<<BB * (NN / 128), 256, 49152>>>(points, w_qkv);
    knn_kernel<<<BB * (NN / 64), 256, 98304>>>(xyz);
    pos_kernel<<<BB * NN * KK / 256, 256, 83200>>>(xyz, w_pos1, b_pos1, w_pos2, b_pos2);
    fused_kernel<<<BB * (NN / 8), 256, 231936>>>(w_att1, b_att1, w_att2, b_att2, out);
}

// round 4
// speedup vs baseline: 1.5760x; 1.0465x over previous
#include <cuda_runtime.h>
#include <math.h>

#define BB 4
#define NN 4096
#define KK 16

typedef unsigned long long ull;

// scratch (device globals: allocation-free per harness rules)
__device__ float g_qkv[BB * NN * 192];            // point-major: [b][n][192]
__device__ int   g_idx[BB * NN * KK];             // [b][n][k]
__device__ float g_pe[(size_t)BB * NN * KK * 64]; // [gp][64]

// ---------------- packed f32x2 helpers ----------------
__device__ __forceinline__ ull ffma2(ull a, ull b, ull c) {
    ull d;
    asm("fma.rn.f32x2 %0, %1, %2, %3;" : "=l"(d) : "l"(a), "l"(b), "l"(c));
    return d;
}
__device__ __forceinline__ ull pack2(float lo, float hi) {
    ull r;
    asm("mov.b64 %0, {%1, %2};" : "=l"(r) : "f"(lo), "f"(hi));
    return r;
}
__device__ __forceinline__ float psum(ull v) {
    float x, y;
    asm("mov.b64 {%0, %1}, %2;" : "=f"(x), "=f"(y) : "l"(v));
    return x + y;
}

// byte-offset swizzle within a 512B row (keeps low 4 bits)
#define SWZ(L) ((L) ^ (((L) >> 3) & 0x70))

// ---------------------------------------------------------------------------
// Kernel 1: qkv = w_qkv @ points, point-major out. 256 thr: o-dim split x2.
// ---------------------------------------------------------------------------
__global__ void qkv_kernel(const float* __restrict__ points,
                           const float* __restrict__ w_qkv) {
    extern __shared__ float sw[];  // 192*64 floats
    int t = threadIdx.x;  // 256
    {
        const float4* a = (const float4*)w_qkv;
        float4* d = (float4*)sw;
        for (int i = t; i < 3072; i += 256) d[i] = a[i];
    }
    __syncthreads();
    int b = blockIdx.x >> 5;
    int n = ((blockIdx.x & 31) << 7) + (t & 127);
    int oh = t >> 7;

    float4 p4[16];
    const float* pb = points + (size_t)b * 64 * NN + n;
#pragma unroll
    for (int d4 = 0; d4 < 16; ++d4) {
        p4[d4].x = pb[(size_t)(4 * d4 + 0) * NN];
        p4[d4].y = pb[(size_t)(4 * d4 + 1) * NN];
        p4[d4].z = pb[(size_t)(4 * d4 + 2) * NN];
        p4[d4].w = pb[(size_t)(4 * d4 + 3) * NN];
    }
    float* outp = g_qkv + ((size_t)(b * NN + n)) * 192 + oh * 96;
    const float* swh = sw + oh * 96 * 64;
    for (int ob = 0; ob < 24; ++ob) {
        float a0 = 0.f, a1 = 0.f, a2 = 0.f, a3 = 0.f;
        const float4* w0 = (const float4*)(swh + (4 * ob + 0) * 64);
        const float4* w1 = (const float4*)(swh + (4 * ob + 1) * 64);
        const float4* w2 = (const float4*)(swh + (4 * ob + 2) * 64);
        const float4* w3 = (const float4*)(swh + (4 * ob + 3) * 64);
#pragma unroll
        for (int d4 = 0; d4 < 16; ++d4) {
            float4 pv = p4[d4];
            float4 wa = w0[d4], wb = w1[d4], wc = w2[d4], wd = w3[d4];
            a0 = fmaf(wa.x, pv.x, a0); a0 = fmaf(wa.y, pv.y, a0);
            a0 = fmaf(wa.z, pv.z, a0); a0 = fmaf(wa.w, pv.w, a0);
            a1 = fmaf(wb.x, pv.x, a1); a1 = fmaf(wb.y, pv.y, a1);
            a1 = fmaf(wb.z, pv.z, a1); a1 = fmaf(wb.w, pv.w, a1);
            a2 = fmaf(wc.x, pv.x, a2); a2 = fmaf(wc.y, pv.y, a2);
            a2 = fmaf(wc.z, pv.z, a2); a2 = fmaf(wc.w, pv.w, a2);
            a3 = fmaf(wd.x, pv.x, a3); a3 = fmaf(wd.y, pv.y, a3);
            a3 = fmaf(wd.z, pv.z, a3); a3 = fmaf(wd.w, pv.w, a3);
        }
        *(float4*)(outp + 4 * ob) = make_float4(a0, a1, a2, a3);
    }
}

// ---------------------------------------------------------------------------
// Kernel 2: KNN (top-16 smallest d2) — verified correct, keep.
// ---------------------------------------------------------------------------
__device__ __forceinline__ void topk_insert(float d2, int m, float bd[16], int bi[16]) {
    bd[15] = d2; bi[15] = m;
#pragma unroll
    for (int i = 15; i > 0; --i) {
        if (bd[i] < bd[i - 1]) {
            float td = bd[i]; bd[i] = bd[i - 1]; bd[i - 1] = td;
            int ti = bi[i]; bi[i] = bi[i - 1]; bi[i - 1] = ti;
        }
    }
}

__global__ void knn_kernel(const float* __restrict__ xyz) {
    extern __shared__ float sm[];
    float* cx = sm;
    float* cy = cx + NN;
    float* cz = cy + NN;
    float* csq = cz + NN;
    float* md = csq + NN;
    int* mi = (int*)(md + 256 * 16);

    int t = threadIdx.x;
    int b = blockIdx.x >> 6;
    int tile = blockIdx.x & 63;
    const float* xb = xyz + (size_t)b * 3 * NN;

    for (int m = t; m < NN; m += 256) {
        float x = xb[m], y = xb[NN + m], z = xb[2 * NN + m];
        cx[m] = x; cy[m] = y; cz[m] = z;
        csq[m] = x * x + y * y + z * z;
    }
    __syncthreads();

    int q = tile * 64 + (t >> 2);
    int p = t & 3;
    float qx = cx[q], qy = cy[q], qz = cz[q];
    float sqq = csq[q];

    float bd[16]; int bi[16];
#pragma unroll
    for (int i = 0; i < 16; ++i) { bd[i] = 3.4e38f; bi[i] = -1; }

    int m0 = p * 1024;
    for (int m = m0; m < m0 + 1024; ++m) {
        float dot = fmaf(qx, cx[m], fmaf(qy, cy[m], qz * cz[m]));
        float d2 = fmaf(-2.f, dot, sqq + csq[m]);
        if (d2 < bd[15]) topk_insert(d2, m, bd, bi);
    }
#pragma unroll
    for (int i = 0; i < 16; ++i) { md[t * 16 + i] = bd[i]; mi[t * 16 + i] = bi[i]; }
    __syncthreads();

    if (p == 0) {
        for (int src = 1; src < 4; ++src) {
            int base = (t + src) * 16;
            for (int e = 0; e < 16; ++e) {
                float d2 = md[base + e];
                if (d2 >= bd[15]) break;
                topk_insert(d2, mi[base + e], bd, bi);
            }
        }
        int* op = g_idx + ((size_t)(b * NN + q)) * KK;
#pragma unroll
        for (int i = 0; i < 16; ++i) op[i] = bi[i];
    }
}

// ---------------------------------------------------------------------------
// Kernel 3: pos-MLP -> g_pe (unchanged).
// ---------------------------------------------------------------------------
__global__ void __launch_bounds__(256, 2)
pos_kernel(const float* __restrict__ xyz,
           const float* __restrict__ w_pos1, const float* __restrict__ b_pos1,
           const float* __restrict__ w_pos2, const float* __restrict__ b_pos2) {
    extern __shared__ float sm[];
    float* swp2 = sm;
    float* swp1 = swp2 + 4096;
    float* sbp1 = swp1 + 192;
    float* sbp2 = sbp1 + 64;
    float* sph  = sbp2 + 64;

    int t = threadIdx.x;
    for (int i = t; i < 4096; i += 256) swp2[i] = w_pos2[i];
    if (t < 192) swp1[t] = w_pos1[t];
    if (t < 64) { sbp1[t] = b_pos1[t]; sbp2[t] = b_pos2[t]; }

    size_t gp0 = (size_t)blockIdx.x * 256;
    int b = (int)(gp0 >> 16);
    {
        size_t gp = gp0 + t;
        int n = (int)((gp >> 4) & 4095);
        int j = g_idx[gp];
        const float* xb = xyz + (size_t)b * 3 * NN;
        float gx0 = xb[n] - xb[j];
        float gx1 = xb[NN + n] - xb[NN + j];
        float gx2 = xb[2 * NN + n] - xb[2 * NN + j];
        __syncthreads();
#pragma unroll 8
        for (int h = 0; h < 64; ++h) {
            float v = fmaf(swp1[h * 3 + 0], gx0, sbp1[h]);
            v = fmaf(swp1[h * 3 + 1], gx1, v);
            v = fmaf(swp1[h * 3 + 2], gx2, v);
            sph[h * 256 + t] = fmaxf(v, 0.f);
        }
    }
    __syncthreads();

    int rg = t >> 5;
    int pg = t & 31;
    int o0 = rg * 8, p0 = pg * 8;
    float acc[8][8];
#pragma unroll
    for (int r = 0; r < 8; ++r)
#pragma unroll
        for (int c = 0; c < 8; ++c) acc[r][c] = sbp2[o0 + r];

    for (int k = 0; k < 64; k += 4) {
        float4 pa[4], pb[4];
#pragma unroll
        for (int kk = 0; kk < 4; ++kk) {
            pa[kk] = *(const float4*)(sph + (k + kk) * 256 + p0);
            pb[kk] = *(const float4*)(sph + (k + kk) * 256 + p0 + 4);
        }
#pragma unroll
        for (int r = 0; r < 8; ++r) {
            float4 w = *(const float4*)(swp2 + (o0 + r) * 64 + k);
#pragma unroll
            for (int c = 0; c < 4; ++c) {
                acc[r][c] = fmaf(w.x, ((const float*)&pa[0])[c], acc[r][c]);
                acc[r][c] = fmaf(w.y, ((const float*)&pa[1])[c], acc[r][c]);
                acc[r][c] = fmaf(w.z, ((const float*)&pa[2])[c], acc[r][c]);
                acc[r][c] = fmaf(w.w, ((const float*)&pa[3])[c], acc[r][c]);
                acc[r][c + 4] = fmaf(w.x, ((const float*)&pb[0])[c], acc[r][c + 4]);
                acc[r][c + 4] = fmaf(w.y, ((const float*)&pb[1])[c], acc[r][c + 4]);
                acc[r][c + 4] = fmaf(w.z, ((const float*)&pb[2])[c], acc[r][c + 4]);
                acc[r][c + 4] = fmaf(w.w, ((const float*)&pb[3])[c], acc[r][c + 4]);
            }
        }
    }
#pragma unroll
    for (int i = 0; i < 8; ++i) {
        float* dst = g_pe + (gp0 + p0 + i) * 64 + o0;
        *(float4*)(dst)     = make_float4(acc[0][i], acc[1][i], acc[2][i], acc[3][i]);
        *(float4*)(dst + 4) = make_float4(acc[4][i], acc[5][i], acc[6][i], acc[7][i]);
    }
}

// ---------------------------------------------------------------------------
// Kernel 4: fused gather + att-MLP + softmax + aggregation.
// 512 threads (4 warps/SMSP for latency hiding), 2 tiles x 4 queries/block.
// k-paired FFMA2, E: 8x4 tiles, F: 4x4 with split-K2.
// ---------------------------------------------------------------------------
__global__ void __launch_bounds__(512, 1)
fused_kernel(const float* __restrict__ w_att1, const float* __restrict__ b_att1,
             const float* __restrict__ w_att2, const float* __restrict__ b_att2,
             float* __restrict__ out) {
    extern __shared__ float sm[];
    float* sw1 = sm;               // 16384  w_att1 [256][64]
    float* sw2 = sw1 + 16384;      // 16384  w_att2 [64][256]
    float* sh2 = sw2 + 16384;      // 16384  h, k-paired [128 kp][64 c x2]
    float* sx2 = sh2 + 16384;      // 4096   x, k-paired [32 kp][64 c x2] ; ssim alias
    float* sv  = sx2 + 4096;       // 4096   v [64 d][64 c]
    float* sb1 = sv + 4096;        // 256
    float* sb2 = sb1 + 256;        // 64
    float* sq  = sb2 + 64;         // 256
    int*   sj  = (int*)(sq + 256); // 64

    int t = threadIdx.x;  // 512
    {
        const float4* a1 = (const float4*)w_att1;
        const float4* a2 = (const float4*)w_att2;
        float4* d1 = (float4*)sw1;
        float4* d2 = (float4*)sw2;
        for (int i = t; i < 4096; i += 512) d1[i] = a1[i];
        for (int i = t; i < 4096; i += 512) d2[i] = a2[i];
    }
    if (t < 256) sb1[t] = b_att1[t];
    if (t < 64) sb2[t] = b_att2[t];

    int b = blockIdx.x >> 9;
    int nb = (blockIdx.x & 511) << 3;

    // common column-group offsets (float index of swizzled 16B slots)
    int cg = t & 15;
    int co0 = SWZ(cg * 32) >> 2;
    int co1 = SWZ(cg * 32 + 16) >> 2;

    for (int tile = 0; tile < 2; ++tile) {
        int n0 = nb + tile * 4;
        __syncthreads();
        if (t < 64) sj[t] = g_idx[((size_t)(b * NN + n0)) * KK + t];
        if (t < 256) sq[t] = g_qkv[((size_t)(b * NN + n0 + (t >> 6))) * 192 + (t & 63)];
        __syncthreads();

        // ---- gather: x = q - k + pe (k-paired, swizzled); v = v + pe ----
        {
            int c = t & 63;
            int d0 = (t >> 6) * 8;
            int j = sj[c];
            const float* qv = sq + (c >> 4) * 64;
            const float* base = g_qkv + ((size_t)(b * NN + j)) * 192;
            const float* pep = g_pe + ((size_t)b * 65536 + (size_t)n0 * 16 + c) * 64;
            int cb = SWZ(c * 8) >> 2;
#pragma unroll
            for (int i = 0; i < 2; ++i) {
                int d = d0 + 4 * i;
                float4 kk = *(const float4*)(base + 64 + d);
                float4 vv = *(const float4*)(base + 128 + d);
                float4 pe = *(const float4*)(pep + d);
                float x0 = qv[d + 0] - kk.x + pe.x;
                float x1 = qv[d + 1] - kk.y + pe.y;
                float x2 = qv[d + 2] - kk.z + pe.z;
                float x3 = qv[d + 3] - kk.w + pe.w;
                *(ull*)(sx2 + (d >> 1) * 128 + cb)       = pack2(x0, x1);
                *(ull*)(sx2 + ((d >> 1) + 1) * 128 + cb) = pack2(x2, x3);
                sv[(d + 0) * 64 + c] = vv.x + pe.x;
                sv[(d + 1) * 64 + c] = vv.y + pe.y;
                sv[(d + 2) * 64 + c] = vv.z + pe.z;
                sv[(d + 3) * 64 + c] = vv.w + pe.w;
            }
        }
        __syncthreads();

        // ---- E: h[256][64] = relu(w1 @ x + b1); tile 8r x 4c ----
        {
            int rg = t >> 4;          // 0..31
            int r0 = rg * 8;
            ull acc[8][4];
#pragma unroll
            for (int r = 0; r < 8; ++r) {
                ull ini = pack2(sb1[r0 + r], 0.f);
#pragma unroll
                for (int c = 0; c < 4; ++c) acc[r][c] = ini;
            }
#pragma unroll 2
            for (int kp2 = 0; kp2 < 16; ++kp2) {
                const float* row0 = sx2 + (2 * kp2) * 128;
                const float* row1 = row0 + 128;
                ulonglong2 a0 = *(const ulonglong2*)(row0 + co0);
                ulonglong2 a1 = *(const ulonglong2*)(row0 + co1);
                ulonglong2 a2 = *(const ulonglong2*)(row1 + co0);
                ulonglong2 a3 = *(const ulonglong2*)(row1 + co1);
#pragma unroll
                for (int r = 0; r < 8; ++r) {
                    ulonglong2 wv = *(const ulonglong2*)(sw1 + (r0 + r) * 64 + kp2 * 4);
                    acc[r][0] = ffma2(wv.x, a0.x, acc[r][0]);
                    acc[r][1] = ffma2(wv.x, a0.y, acc[r][1]);
                    acc[r][2] = ffma2(wv.x, a1.x, acc[r][2]);
                    acc[r][3] = ffma2(wv.x, a1.y, acc[r][3]);
                    acc[r][0] = ffma2(wv.y, a2.x, acc[r][0]);
                    acc[r][1] = ffma2(wv.y, a2.y, acc[r][1]);
                    acc[r][2] = ffma2(wv.y, a3.x, acc[r][2]);
                    acc[r][3] = ffma2(wv.y, a3.y, acc[r][3]);
                }
            }
            // epilogue: relu(lo+hi), pack row-pairs, store to sh2 (k-paired)
#pragma unroll
            for (int rp = 0; rp < 4; ++rp) {
                float* dst = sh2 + (rg * 4 + rp) * 128;
                float hA0 = fmaxf(psum(acc[2 * rp][0]), 0.f);
                float hB0 = fmaxf(psum(acc[2 * rp + 1][0]), 0.f);
                float hA1 = fmaxf(psum(acc[2 * rp][1]), 0.f);
                float hB1 = fmaxf(psum(acc[2 * rp + 1][1]), 0.f);
                float hA2 = fmaxf(psum(acc[2 * rp][2]), 0.f);
                float hB2 = fmaxf(psum(acc[2 * rp + 1][2]), 0.f);
                float hA3 = fmaxf(psum(acc[2 * rp][3]), 0.f);
                float hB3 = fmaxf(psum(acc[2 * rp + 1][3]), 0.f);
                ulonglong2 s0, s1;
                s0.x = pack2(hA0, hB0); s0.y = pack2(hA1, hB1);
                s1.x = pack2(hA2, hB2); s1.y = pack2(hA3, hB3);
                *(ulonglong2*)(dst + co0) = s0;
                *(ulonglong2*)(dst + co1) = s1;
            }
        }
        __syncthreads();

        // ---- F: sim[64][64] = w2 @ h + b2; tile 4r x 4c, split-K2 ----
        {
            int half = t >> 8;
            int tt = t & 255;
            int rg4 = tt >> 4;     // 0..15
            int cgf = tt & 15;
            int cf0 = SWZ(cgf * 32) >> 2;
            int cf1 = SWZ(cgf * 32 + 16) >> 2;
            int r0 = rg4 * 4;
            ull acc[4][4];
#pragma unroll
            for (int r = 0; r < 4; ++r)
#pragma unroll
                for (int c = 0; c < 4; ++c) acc[r][c] = 0ULL;

            const float* swr = sw2 + half * 128;
            const float* shb = sh2 + half * 64 * 128;
#pragma unroll 2
            for (int kp2 = 0; kp2 < 32; ++kp2) {
                const float* row0 = shb + (2 * kp2) * 128;
                const float* row1 = row0 + 128;
                ulonglong2 a0 = *(const ulonglong2*)(row0 + cf0);
                ulonglong2 a1 = *(const ulonglong2*)(row0 + cf1);
                ulonglong2 a2 = *(const ulonglong2*)(row1 + cf0);
                ulonglong2 a3 = *(const ulonglong2*)(row1 + cf1);
#pragma unroll
                for (int r = 0; r < 4; ++r) {
                    ulonglong2 wv = *(const ulonglong2*)(swr + (r0 + r) * 256 + kp2 * 4);
                    acc[r][0] = ffma2(wv.x, a0.x, acc[r][0]);
                    acc[r][1] = ffma2(wv.x, a0.y, acc[r][1]);
                    acc[r][2] = ffma2(wv.x, a1.x, acc[r][2]);
                    acc[r][3] = ffma2(wv.x, a1.y, acc[r][3]);
                    acc[r][0] = ffma2(wv.y, a2.x, acc[r][0]);
                    acc[r][1] = ffma2(wv.y, a2.y, acc[r][1]);
                    acc[r][2] = ffma2(wv.y, a3.x, acc[r][2]);
                    acc[r][3] = ffma2(wv.y, a3.y, acc[r][3]);
                }
            }
            float* ssim = sx2;  // alias (x consumed)
            if (half == 0) {
#pragma unroll
                for (int r = 0; r < 4; ++r) {
                    float bias = sb2[r0 + r];
#pragma unroll
                    for (int c = 0; c < 4; ++c)
                        ssim[(r0 + r) * 64 + cgf * 4 + c] = bias + psum(acc[r][c]);
                }
            }
            __syncthreads();
            if (half == 1) {
#pragma unroll
                for (int r = 0; r < 4; ++r)
#pragma unroll
                    for (int c = 0; c < 4; ++c)
                        ssim[(r0 + r) * 64 + cgf * 4 + c] += psum(acc[r][c]);
            }
        }
        __syncthreads();

        // ---- softmax over K + weighted sum ----
        if (t < 256) {
            int d = t >> 2, qq = t & 3;
            const float* sp = sx2 + d * 64 + qq * 16;
            const float* vp = sv + d * 64 + qq * 16;
            float mx = -3.4e38f;
#pragma unroll
            for (int k = 0; k < 16; ++k) mx = fmaxf(mx, sp[k]);
            float s = 0.f, a = 0.f;
#pragma unroll
            for (int k = 0; k < 16; ++k) {
                float e = __expf(sp[k] - mx);
                s += e;
                a = fmaf(e, vp[k], a);
            }
            out[((size_t)(b * 64 + d)) * NN + n0 + qq] = a / s;
        }
    }
}

// ---------------------------------------------------------------------------
extern "C" void kernel_launch(void* const* d_in, const int* in_sizes, int n_in,
                              void* d_out, int out_size) {
    (void)in_sizes; (void)n_in; (void)out_size;
    const float* xyz    = (const float*)d_in[0];
    const float* points = (const float*)d_in[1];
    const float* w_qkv  = (const float*)d_in[2];
    const float* w_pos1 = (const float*)d_in[3];
    const float* b_pos1 = (const float*)d_in[4];
    const float* w_pos2 = (const float*)d_in[5];
    const float* b_pos2 = (const float*)d_in[6];
    const float* w_att1 = (const float*)d_in[7];
    const float* b_att1 = (const float*)d_in[8];
    const float* w_att2 = (const float*)d_in[9];
    const float* b_att2 = (const float*)d_in[10];
    float* out = (float*)d_out;

    cudaFuncSetAttribute(qkv_kernel, cudaFuncAttributeMaxDynamicSharedMemorySize, 49152);
    cudaFuncSetAttribute(knn_kernel, cudaFuncAttributeMaxDynamicSharedMemorySize, 98304);
    cudaFuncSetAttribute(pos_kernel, cudaFuncAttributeMaxDynamicSharedMemorySize, 83200);
    cudaFuncSetAttribute(fused_kernel, cudaFuncAttributeMaxDynamicSharedMemorySize, 231936);

    qkv_kernel<<<BB * (NN / 128), 256, 49152>>>(points, w_qkv);
    knn_kernel<<<BB * (NN / 64), 256, 98304>>>(xyz);
    pos_kernel<<<BB * NN * KK / 256, 256, 83200>>>(xyz, w_pos1, b_pos1, w_pos2, b_pos2);
    fused_kernel<<<BB * (NN / 8), 512, 231936>>>(w_att1, b_att1, w_att2, b_att2, out);
}

// round 5
// speedup vs baseline: 1.6246x; 1.0308x over previous
#include <cuda_runtime.h>
#include <math.h>

#define BB 4
#define NN 4096
#define KK 16

typedef unsigned long long ull;

// scratch (device globals: allocation-free per harness rules)
__device__ float g_qkv[BB * NN * 192];            // point-major: [b][n][192]
__device__ int   g_idx[BB * NN * KK];             // [b][n][k]
__device__ float g_pe[(size_t)BB * NN * KK * 64]; // [gp][64]

// ---------------- packed f32x2 helpers ----------------
__device__ __forceinline__ ull ffma2(ull a, ull b, ull c) {
    ull d;
    asm("fma.rn.f32x2 %0, %1, %2, %3;" : "=l"(d) : "l"(a), "l"(b), "l"(c));
    return d;
}
__device__ __forceinline__ ull pack2(float lo, float hi) {
    ull r;
    asm("mov.b64 %0, {%1, %2};" : "=l"(r) : "f"(lo), "f"(hi));
    return r;
}
__device__ __forceinline__ float psum(ull v) {
    float x, y;
    asm("mov.b64 {%0, %1}, %2;" : "=f"(x), "=f"(y) : "l"(v));
    return x + y;
}

// byte-offset swizzle within a 512B row (keeps low 4 bits)
#define SWZ(L) ((L) ^ (((L) >> 3) & 0x70))

// ---------------------------------------------------------------------------
// Kernel 1: qkv = w_qkv @ points. grid 256 (64 points/block), 256 thr:
// 64 points x 4 o-groups of 48 outputs.
// ---------------------------------------------------------------------------
__global__ void qkv_kernel(const float* __restrict__ points,
                           const float* __restrict__ w_qkv) {
    extern __shared__ float sw[];  // 192*64 floats
    int t = threadIdx.x;  // 256
    {
        const float4* a = (const float4*)w_qkv;
        float4* d = (float4*)sw;
        for (int i = t; i < 3072; i += 256) d[i] = a[i];
    }
    __syncthreads();
    int b = blockIdx.x >> 6;
    int n = ((blockIdx.x & 63) << 6) + (t & 63);
    int oh = t >> 6;  // 0..3

    float4 p4[16];
    const float* pb = points + (size_t)b * 64 * NN + n;
#pragma unroll
    for (int d4 = 0; d4 < 16; ++d4) {
        p4[d4].x = pb[(size_t)(4 * d4 + 0) * NN];
        p4[d4].y = pb[(size_t)(4 * d4 + 1) * NN];
        p4[d4].z = pb[(size_t)(4 * d4 + 2) * NN];
        p4[d4].w = pb[(size_t)(4 * d4 + 3) * NN];
    }
    float* outp = g_qkv + ((size_t)(b * NN + n)) * 192 + oh * 48;
    const float* swh = sw + oh * 48 * 64;
    for (int ob = 0; ob < 12; ++ob) {
        float a0 = 0.f, a1 = 0.f, a2 = 0.f, a3 = 0.f;
        const float4* w0 = (const float4*)(swh + (4 * ob + 0) * 64);
        const float4* w1 = (const float4*)(swh + (4 * ob + 1) * 64);
        const float4* w2 = (const float4*)(swh + (4 * ob + 2) * 64);
        const float4* w3 = (const float4*)(swh + (4 * ob + 3) * 64);
#pragma unroll
        for (int d4 = 0; d4 < 16; ++d4) {
            float4 pv = p4[d4];
            float4 wa = w0[d4], wb = w1[d4], wc = w2[d4], wd = w3[d4];
            a0 = fmaf(wa.x, pv.x, a0); a0 = fmaf(wa.y, pv.y, a0);
            a0 = fmaf(wa.z, pv.z, a0); a0 = fmaf(wa.w, pv.w, a0);
            a1 = fmaf(wb.x, pv.x, a1); a1 = fmaf(wb.y, pv.y, a1);
            a1 = fmaf(wb.z, pv.z, a1); a1 = fmaf(wb.w, pv.w, a1);
            a2 = fmaf(wc.x, pv.x, a2); a2 = fmaf(wc.y, pv.y, a2);
            a2 = fmaf(wc.z, pv.z, a2); a2 = fmaf(wc.w, pv.w, a2);
            a3 = fmaf(wd.x, pv.x, a3); a3 = fmaf(wd.y, pv.y, a3);
            a3 = fmaf(wd.z, pv.z, a3); a3 = fmaf(wd.w, pv.w, a3);
        }
        *(float4*)(outp + 4 * ob) = make_float4(a0, a1, a2, a3);
    }
}

// ---------------------------------------------------------------------------
// Kernel 2: KNN (top-16 smallest d2), candidate loop unrolled x2.
// ---------------------------------------------------------------------------
__device__ __forceinline__ void topk_insert(float d2, int m, float bd[16], int bi[16]) {
    bd[15] = d2; bi[15] = m;
#pragma unroll
    for (int i = 15; i > 0; --i) {
        if (bd[i] < bd[i - 1]) {
            float td = bd[i]; bd[i] = bd[i - 1]; bd[i - 1] = td;
            int ti = bi[i]; bi[i] = bi[i - 1]; bi[i - 1] = ti;
        }
    }
}

__global__ void knn_kernel(const float* __restrict__ xyz) {
    extern __shared__ float sm[];
    float* cx = sm;
    float* cy = cx + NN;
    float* cz = cy + NN;
    float* csq = cz + NN;
    float* md = csq + NN;
    int* mi = (int*)(md + 256 * 16);

    int t = threadIdx.x;
    int b = blockIdx.x >> 6;
    int tile = blockIdx.x & 63;
    const float* xb = xyz + (size_t)b * 3 * NN;

    for (int m = t; m < NN; m += 256) {
        float x = xb[m], y = xb[NN + m], z = xb[2 * NN + m];
        cx[m] = x; cy[m] = y; cz[m] = z;
        csq[m] = x * x + y * y + z * z;
    }
    __syncthreads();

    int q = tile * 64 + (t >> 2);
    int p = t & 3;
    float qx = cx[q], qy = cy[q], qz = cz[q];
    float sqq = csq[q];

    float bd[16]; int bi[16];
#pragma unroll
    for (int i = 0; i < 16; ++i) { bd[i] = 3.4e38f; bi[i] = -1; }

    int m0 = p * 1024;
    for (int m = m0; m < m0 + 1024; m += 2) {
        float dot0 = fmaf(qx, cx[m], fmaf(qy, cy[m], qz * cz[m]));
        float dot1 = fmaf(qx, cx[m + 1], fmaf(qy, cy[m + 1], qz * cz[m + 1]));
        float d20 = fmaf(-2.f, dot0, sqq + csq[m]);
        float d21 = fmaf(-2.f, dot1, sqq + csq[m + 1]);
        if (d20 < bd[15]) topk_insert(d20, m, bd, bi);
        if (d21 < bd[15]) topk_insert(d21, m + 1, bd, bi);
    }
#pragma unroll
    for (int i = 0; i < 16; ++i) { md[t * 16 + i] = bd[i]; mi[t * 16 + i] = bi[i]; }
    __syncthreads();

    if (p == 0) {
        for (int src = 1; src < 4; ++src) {
            int base = (t + src) * 16;
            for (int e = 0; e < 16; ++e) {
                float d2 = md[base + e];
                if (d2 >= bd[15]) break;
                topk_insert(d2, mi[base + e], bd, bi);
            }
        }
        int* op = g_idx + ((size_t)(b * NN + q)) * KK;
#pragma unroll
        for (int i = 0; i < 16; ++i) op[i] = bi[i];
    }
}

// ---------------------------------------------------------------------------
// Kernel 3: pos-MLP -> g_pe (unchanged).
// ---------------------------------------------------------------------------
__global__ void __launch_bounds__(256, 2)
pos_kernel(const float* __restrict__ xyz,
           const float* __restrict__ w_pos1, const float* __restrict__ b_pos1,
           const float* __restrict__ w_pos2, const float* __restrict__ b_pos2) {
    extern __shared__ float sm[];
    float* swp2 = sm;
    float* swp1 = swp2 + 4096;
    float* sbp1 = swp1 + 192;
    float* sbp2 = sbp1 + 64;
    float* sph  = sbp2 + 64;

    int t = threadIdx.x;
    for (int i = t; i < 4096; i += 256) swp2[i] = w_pos2[i];
    if (t < 192) swp1[t] = w_pos1[t];
    if (t < 64) { sbp1[t] = b_pos1[t]; sbp2[t] = b_pos2[t]; }

    size_t gp0 = (size_t)blockIdx.x * 256;
    int b = (int)(gp0 >> 16);
    {
        size_t gp = gp0 + t;
        int n = (int)((gp >> 4) & 4095);
        int j = g_idx[gp];
        const float* xb = xyz + (size_t)b * 3 * NN;
        float gx0 = xb[n] - xb[j];
        float gx1 = xb[NN + n] - xb[NN + j];
        float gx2 = xb[2 * NN + n] - xb[2 * NN + j];
        __syncthreads();
#pragma unroll 8
        for (int h = 0; h < 64; ++h) {
            float v = fmaf(swp1[h * 3 + 0], gx0, sbp1[h]);
            v = fmaf(swp1[h * 3 + 1], gx1, v);
            v = fmaf(swp1[h * 3 + 2], gx2, v);
            sph[h * 256 + t] = fmaxf(v, 0.f);
        }
    }
    __syncthreads();

    int rg = t >> 5;
    int pg = t & 31;
    int o0 = rg * 8, p0 = pg * 8;
    float acc[8][8];
#pragma unroll
    for (int r = 0; r < 8; ++r)
#pragma unroll
        for (int c = 0; c < 8; ++c) acc[r][c] = sbp2[o0 + r];

    for (int k = 0; k < 64; k += 4) {
        float4 pa[4], pb[4];
#pragma unroll
        for (int kk = 0; kk < 4; ++kk) {
            pa[kk] = *(const float4*)(sph + (k + kk) * 256 + p0);
            pb[kk] = *(const float4*)(sph + (k + kk) * 256 + p0 + 4);
        }
#pragma unroll
        for (int r = 0; r < 8; ++r) {
            float4 w = *(const float4*)(swp2 + (o0 + r) * 64 + k);
#pragma unroll
            for (int c = 0; c < 4; ++c) {
                acc[r][c] = fmaf(w.x, ((const float*)&pa[0])[c], acc[r][c]);
                acc[r][c] = fmaf(w.y, ((const float*)&pa[1])[c], acc[r][c]);
                acc[r][c] = fmaf(w.z, ((const float*)&pa[2])[c], acc[r][c]);
                acc[r][c] = fmaf(w.w, ((const float*)&pa[3])[c], acc[r][c]);
                acc[r][c + 4] = fmaf(w.x, ((const float*)&pb[0])[c], acc[r][c + 4]);
                acc[r][c + 4] = fmaf(w.y, ((const float*)&pb[1])[c], acc[r][c + 4]);
                acc[r][c + 4] = fmaf(w.z, ((const float*)&pb[2])[c], acc[r][c + 4]);
                acc[r][c + 4] = fmaf(w.w, ((const float*)&pb[3])[c], acc[r][c + 4]);
            }
        }
    }
#pragma unroll
    for (int i = 0; i < 8; ++i) {
        float* dst = g_pe + (gp0 + p0 + i) * 64 + o0;
        *(float4*)(dst)     = make_float4(acc[0][i], acc[1][i], acc[2][i], acc[3][i]);
        *(float4*)(dst + 4) = make_float4(acc[4][i], acc[5][i], acc[6][i], acc[7][i]);
    }
}

// ---------------------------------------------------------------------------
// Kernel 4: fused att-MLP. 512 threads, 4 tiles x 4 queries/block.
// Software-pipelined k-paired FFMA2 (B double-buffer + weight rotation),
// gather LDGs issued before the tile barrier.
// ---------------------------------------------------------------------------
__global__ void __launch_bounds__(512, 1)
fused_kernel(const float* __restrict__ w_att1, const float* __restrict__ b_att1,
             const float* __restrict__ w_att2, const float* __restrict__ b_att2,
             float* __restrict__ out) {
    extern __shared__ float sm[];
    float* sw1 = sm;               // w_att1 [256][64]
    float* sw2 = sw1 + 16384;      // w_att2 [64][256]
    float* sh2 = sw2 + 16384;      // h, k-paired [128 kp][64 c x2]
    float* sx2 = sh2 + 16384;      // x, k-paired [32 kp][64 c x2] ; ssim alias
    float* sv  = sx2 + 4096;       // v [64 d][64 c]
    float* sb1 = sv + 4096;        // 256
    float* sb2 = sb1 + 256;        // 64

    int t = threadIdx.x;  // 512
    {
        const float4* a1 = (const float4*)w_att1;
        const float4* a2 = (const float4*)w_att2;
        float4* d1 = (float4*)sw1;
        float4* d2 = (float4*)sw2;
        for (int i = t; i < 4096; i += 512) d1[i] = a1[i];
        for (int i = t; i < 4096; i += 512) d2[i] = a2[i];
    }
    if (t < 256) sb1[t] = b_att1[t];
    if (t < 64) sb2[t] = b_att2[t];

    int b = blockIdx.x >> 8;          // 256 blocks per batch
    int nb = (blockIdx.x & 255) << 4; // 16 queries per block

    // swizzled column-group offsets for E (cg handles cols 4cg..4cg+3)
    int cg = t & 15;
    int co0 = SWZ(cg * 32) >> 2;
    int co1 = SWZ(cg * 32 + 16) >> 2;

    for (int tile = 0; tile < 4; ++tile) {
        int n0 = nb + tile * 4;

        // ---- gather LDGs (before barrier: overlap prev tile's epilogue) ----
        int c = t & 63;
        int d0g = (t >> 6) * 8;
        int j = g_idx[((size_t)(b * NN + n0)) * KK + c];
        const float* base = g_qkv + ((size_t)(b * NN + j)) * 192;
        const float* qrow = g_qkv + ((size_t)(b * NN + n0 + (c >> 4))) * 192;
        const float* pep = g_pe + ((size_t)b * 65536 + (size_t)n0 * 16 + c) * 64;
        float4 kk0 = *(const float4*)(base + 64 + d0g);
        float4 kk1 = *(const float4*)(base + 64 + d0g + 4);
        float4 vv0 = *(const float4*)(base + 128 + d0g);
        float4 vv1 = *(const float4*)(base + 128 + d0g + 4);
        float4 pe0 = *(const float4*)(pep + d0g);
        float4 pe1 = *(const float4*)(pep + d0g + 4);
        float4 q0 = *(const float4*)(qrow + d0g);
        float4 q1 = *(const float4*)(qrow + d0g + 4);

        __syncthreads();  // prev tile fully consumed (and weights loaded, tile 0)

        {
            int cb = SWZ(c * 8) >> 2;
            *(ull*)(sx2 + (d0g >> 1) * 128 + cb)       = pack2(q0.x - kk0.x + pe0.x, q0.y - kk0.y + pe0.y);
            *(ull*)(sx2 + ((d0g >> 1) + 1) * 128 + cb) = pack2(q0.z - kk0.z + pe0.z, q0.w - kk0.w + pe0.w);
            *(ull*)(sx2 + ((d0g >> 1) + 2) * 128 + cb) = pack2(q1.x - kk1.x + pe1.x, q1.y - kk1.y + pe1.y);
            *(ull*)(sx2 + ((d0g >> 1) + 3) * 128 + cb) = pack2(q1.z - kk1.z + pe1.z, q1.w - kk1.w + pe1.w);
            sv[(d0g + 0) * 64 + c] = vv0.x + pe0.x;
            sv[(d0g + 1) * 64 + c] = vv0.y + pe0.y;
            sv[(d0g + 2) * 64 + c] = vv0.z + pe0.z;
            sv[(d0g + 3) * 64 + c] = vv0.w + pe0.w;
            sv[(d0g + 4) * 64 + c] = vv1.x + pe1.x;
            sv[(d0g + 5) * 64 + c] = vv1.y + pe1.y;
            sv[(d0g + 6) * 64 + c] = vv1.z + pe1.z;
            sv[(d0g + 7) * 64 + c] = vv1.w + pe1.w;
        }
        __syncthreads();

        // ---- E: h[256][64] = relu(w1 @ x + b1); 8r x 4c, pipelined ----
        {
            int rg = t >> 4;
            int r0 = rg * 8;
            ull acc[8][4];
#pragma unroll
            for (int r = 0; r < 8; ++r) {
                ull ini = pack2(sb1[r0 + r], 0.f);
#pragma unroll
                for (int cc = 0; cc < 4; ++cc) acc[r][cc] = ini;
            }
            ulonglong2 a0 = *(const ulonglong2*)(sx2 + co0);
            ulonglong2 a1 = *(const ulonglong2*)(sx2 + co1);
            ulonglong2 a2 = *(const ulonglong2*)(sx2 + 128 + co0);
            ulonglong2 a3 = *(const ulonglong2*)(sx2 + 128 + co1);
#pragma unroll 2
            for (int kp2 = 0; kp2 < 16; ++kp2) {
                int nr = (2 * kp2 + 2) & 31;  // wrapped prefetch row (safe)
                const float* rp0 = sx2 + nr * 128;
                ulonglong2 p0_ = *(const ulonglong2*)(rp0 + co0);
                ulonglong2 p1_ = *(const ulonglong2*)(rp0 + co1);
                ulonglong2 p2_ = *(const ulonglong2*)(rp0 + 128 + co0);
                ulonglong2 p3_ = *(const ulonglong2*)(rp0 + 128 + co1);
                const float* wb_ = sw1 + r0 * 64 + kp2 * 4;
                ulonglong2 wv = *(const ulonglong2*)(wb_);
#pragma unroll
                for (int r = 0; r < 8; ++r) {
                    ulonglong2 wn = (r < 7) ? *(const ulonglong2*)(wb_ + (r + 1) * 64) : wv;
                    acc[r][0] = ffma2(wv.x, a0.x, acc[r][0]);
                    acc[r][1] = ffma2(wv.x, a0.y, acc[r][1]);
                    acc[r][2] = ffma2(wv.x, a1.x, acc[r][2]);
                    acc[r][3] = ffma2(wv.x, a1.y, acc[r][3]);
                    acc[r][0] = ffma2(wv.y, a2.x, acc[r][0]);
                    acc[r][1] = ffma2(wv.y, a2.y, acc[r][1]);
                    acc[r][2] = ffma2(wv.y, a3.x, acc[r][2]);
                    acc[r][3] = ffma2(wv.y, a3.y, acc[r][3]);
                    wv = wn;
                }
                a0 = p0_; a1 = p1_; a2 = p2_; a3 = p3_;
            }
#pragma unroll
            for (int rp = 0; rp < 4; ++rp) {
                float* dst = sh2 + (rg * 4 + rp) * 128;
                float hA0 = fmaxf(psum(acc[2 * rp][0]), 0.f);
                float hB0 = fmaxf(psum(acc[2 * rp + 1][0]), 0.f);
                float hA1 = fmaxf(psum(acc[2 * rp][1]), 0.f);
                float hB1 = fmaxf(psum(acc[2 * rp + 1][1]), 0.f);
                float hA2 = fmaxf(psum(acc[2 * rp][2]), 0.f);
                float hB2 = fmaxf(psum(acc[2 * rp + 1][2]), 0.f);
                float hA3 = fmaxf(psum(acc[2 * rp][3]), 0.f);
                float hB3 = fmaxf(psum(acc[2 * rp + 1][3]), 0.f);
                ulonglong2 s0, s1;
                s0.x = pack2(hA0, hB0); s0.y = pack2(hA1, hB1);
                s1.x = pack2(hA2, hB2); s1.y = pack2(hA3, hB3);
                *(ulonglong2*)(dst + co0) = s0;
                *(ulonglong2*)(dst + co1) = s1;
            }
        }
        __syncthreads();

        // ---- F: sim[64][64] = w2 @ h + b2; 4r x 4c, split-K2, pipelined ----
        {
            int half = t >> 8;
            int tt = t & 255;
            int rg4 = tt >> 4;
            int cgf = tt & 15;
            int cf0 = SWZ(cgf * 32) >> 2;
            int cf1 = SWZ(cgf * 32 + 16) >> 2;
            int r0 = rg4 * 4;
            ull acc[4][4];
#pragma unroll
            for (int r = 0; r < 4; ++r)
#pragma unroll
                for (int cc = 0; cc < 4; ++cc) acc[r][cc] = 0ULL;

            const float* swr = sw2 + half * 128;
            const float* shb = sh2 + half * 64 * 128;
            ulonglong2 a0 = *(const ulonglong2*)(shb + cf0);
            ulonglong2 a1 = *(const ulonglong2*)(shb + cf1);
            ulonglong2 a2 = *(const ulonglong2*)(shb + 128 + cf0);
            ulonglong2 a3 = *(const ulonglong2*)(shb + 128 + cf1);
#pragma unroll 2
            for (int kp2 = 0; kp2 < 32; ++kp2) {
                int nr = (2 * kp2 + 2) & 63;  // wrapped prefetch row (safe)
                const float* rp0 = shb + nr * 128;
                ulonglong2 p0_ = *(const ulonglong2*)(rp0 + cf0);
                ulonglong2 p1_ = *(const ulonglong2*)(rp0 + cf1);
                ulonglong2 p2_ = *(const ulonglong2*)(rp0 + 128 + cf0);
                ulonglong2 p3_ = *(const ulonglong2*)(rp0 + 128 + cf1);
                const float* wb_ = swr + r0 * 256 + kp2 * 4;
                ulonglong2 wv = *(const ulonglong2*)(wb_);
#pragma unroll
                for (int r = 0; r < 4; ++r) {
                    ulonglong2 wn = (r < 3) ? *(const ulonglong2*)(wb_ + (r + 1) * 256) : wv;
                    acc[r][0] = ffma2(wv.x, a0.x, acc[r][0]);
                    acc[r][1] = ffma2(wv.x, a0.y, acc[r][1]);
                    acc[r][2] = ffma2(wv.x, a1.x, acc[r][2]);
                    acc[r][3] = ffma2(wv.x, a1.y, acc[r][3]);
                    acc[r][0] = ffma2(wv.y, a2.x, acc[r][0]);
                    acc[r][1] = ffma2(wv.y, a2.y, acc[r][1]);
                    acc[r][2] = ffma2(wv.y, a3.x, acc[r][2]);
                    acc[r][3] = ffma2(wv.y, a3.y, acc[r][3]);
                    wv = wn;
                }
                a0 = p0_; a1 = p1_; a2 = p2_; a3 = p3_;
            }
            float* ssim = sx2;  // alias (x consumed)
            if (half == 0) {
#pragma unroll
                for (int r = 0; r < 4; ++r) {
                    float bias = sb2[r0 + r];
#pragma unroll
                    for (int cc = 0; cc < 4; ++cc)
                        ssim[(r0 + r) * 64 + cgf * 4 + cc] = bias + psum(acc[r][cc]);
                }
            }
            __syncthreads();
            if (half == 1) {
#pragma unroll
                for (int r = 0; r < 4; ++r)
#pragma unroll
                    for (int cc = 0; cc < 4; ++cc)
                        ssim[(r0 + r) * 64 + cgf * 4 + cc] += psum(acc[r][cc]);
            }
        }
        __syncthreads();

        // ---- softmax over K + weighted sum ----
        if (t < 256) {
            int d = t >> 2, qq = t & 3;
            const float* sp = sx2 + d * 64 + qq * 16;
            const float* vp = sv + d * 64 + qq * 16;
            float mx = -3.4e38f;
#pragma unroll
            for (int k = 0; k < 16; ++k) mx = fmaxf(mx, sp[k]);
            float s = 0.f, a = 0.f;
#pragma unroll
            for (int k = 0; k < 16; ++k) {
                float e = __expf(sp[k] - mx);
                s += e;
                a = fmaf(e, vp[k], a);
            }
            out[((size_t)(b * 64 + d)) * NN + n0 + qq] = a / s;
        }
    }
}

// ---------------------------------------------------------------------------
extern "C" void kernel_launch(void* const* d_in, const int* in_sizes, int n_in,
                              void* d_out, int out_size) {
    (void)in_sizes; (void)n_in; (void)out_size;
    const float* xyz    = (const float*)d_in[0];
    const float* points = (const float*)d_in[1];
    const float* w_qkv  = (const float*)d_in[2];
    const float* w_pos1 = (const float*)d_in[3];
    const float* b_pos1 = (const float*)d_in[4];
    const float* w_pos2 = (const float*)d_in[5];
    const float* b_pos2 = (const float*)d_in[6];
    const float* w_att1 = (const float*)d_in[7];
    const float* b_att1 = (const float*)d_in[8];
    const float* w_att2 = (const float*)d_in[9];
    const float* b_att2 = (const float*)d_in[10];
    float* out = (float*)d_out;

    cudaFuncSetAttribute(qkv_kernel, cudaFuncAttributeMaxDynamicSharedMemorySize, 49152);
    cudaFuncSetAttribute(knn_kernel, cudaFuncAttributeMaxDynamicSharedMemorySize, 98304);
    cudaFuncSetAttribute(pos_kernel, cudaFuncAttributeMaxDynamicSharedMemorySize, 83200);
    cudaFuncSetAttribute(fused_kernel, cudaFuncAttributeMaxDynamicSharedMemorySize, 230656);

    qkv_kernel<<<BB * (NN / 64), 256, 49152>>>(points, w_qkv);
    knn_kernel<<<BB * (NN / 64), 256, 98304>>>(xyz);
    pos_kernel<<<BB * NN * KK / 256, 256, 83200>>>(xyz, w_pos1, b_pos1, w_pos2, b_pos2);
    fused_kernel<<<BB * (NN / 16), 512, 230656>>>(w_att1, b_att1, w_att2, b_att2, out);
}

// round 7
// speedup vs baseline: 2.2008x; 1.3547x over previous
#include <cuda_runtime.h>
#include <cuda_bf16.h>
#include <math.h>

#define BB 4
#define NN 4096
#define KK 16

typedef unsigned long long ull;
typedef unsigned int uint;

// scratch (device globals: allocation-free per harness rules)
__device__ float g_qkv[BB * NN * 192];            // point-major: [b][n][192]
__device__ int   g_idx[BB * NN * KK];             // [b][n][k]
__device__ float g_pe[(size_t)BB * NN * KK * 64]; // [gp][64]

// ============================ mma.sync helpers =============================
__device__ __forceinline__ uint smem_u32(const void* p) {
    uint a;
    asm("{ .reg .u64 t; cvta.to.shared.u64 t, %1; cvt.u32.u64 %0, t; }"
        : "=r"(a) : "l"(p));
    return a;
}
__device__ __forceinline__ void ldsm4(uint* r, uint addr) {
    asm volatile("ldmatrix.sync.aligned.m8n8.x4.shared.b16 {%0,%1,%2,%3}, [%4];"
                 : "=r"(r[0]), "=r"(r[1]), "=r"(r[2]), "=r"(r[3]) : "r"(addr));
}
__device__ __forceinline__ void mma_bf16(float* d, const uint* a, const uint* b) {
    asm volatile(
        "mma.sync.aligned.m16n8k16.row.col.f32.bf16.bf16.f32 "
        "{%0,%1,%2,%3},{%4,%5,%6,%7},{%8,%9},{%0,%1,%2,%3};"
        : "+f"(d[0]), "+f"(d[1]), "+f"(d[2]), "+f"(d[3])
        : "r"(a[0]), "r"(a[1]), "r"(a[2]), "r"(a[3]), "r"(b[0]), "r"(b[1]));
}
__device__ __forceinline__ uint bf2(float a, float b) {
    unsigned short ha = __bfloat16_as_ushort(__float2bfloat16_rn(a));
    unsigned short hb = __bfloat16_as_ushort(__float2bfloat16_rn(b));
    return (uint)ha | ((uint)hb << 16);
}
__device__ __forceinline__ float bfres(float a) {
    return a - __bfloat162float(__float2bfloat16_rn(a));
}
// A-fragment ldmatrix.x4 address (16x16 tile at (row0, byte L0), row width W)
__device__ __forceinline__ uint afrag_addr(uint base, int W, int row0, int L0, int lane) {
    int row = row0 + (lane & 7) + ((lane >> 3) & 1) * 8;
    int l = L0 + (lane >> 4) * 16;
    return base + row * W + (l ^ ((row & 7) << 4));
}
// B-fragment ldmatrix.x4 address (two n-tiles n0..n0+15, k16 at byte L0)
__device__ __forceinline__ uint bfrag_addr(uint base, int W, int n0, int L0, int lane) {
    int row = n0 + (lane & 7) + (lane >> 4) * 8;
    int l = L0 + ((lane >> 3) & 1) * 16;
    return base + row * W + (l ^ ((row & 7) << 4));
}

// smem byte offsets
#define OFF_W1H 0u        /* [256 r][64 k] bf16 swz, 32768 */
#define OFF_W1L 32768u
#define OFF_W2H 65536u    /* [64 o][256 k] bf16 swz, 32768 */
#define OFF_W2L 98304u
#define OFF_XH  131072u   /* [128 c][64 d] bf16 swz, 16384 */
#define OFF_XL  147456u
#define OFF_HH  163840u   /* [128 c][128 r-half] bf16 swz, 32768 */
#define OFF_HL  196608u
#define OFF_SIM 163840u   /* reuse H: sim [128][68] fp32 = 34816 */
#define OFF_B1  229376u
#define OFF_B2  230400u
#define OFF_SJ  230656u   /* int[128] */
#define SMEM_TC 231168u

// ---------------------------------------------------------------------------
// Kernel 1: qkv (unchanged)
// ---------------------------------------------------------------------------
__global__ void qkv_kernel(const float* __restrict__ points,
                           const float* __restrict__ w_qkv) {
    extern __shared__ float sw[];
    int t = threadIdx.x;
    {
        const float4* a = (const float4*)w_qkv;
        float4* d = (float4*)sw;
        for (int i = t; i < 3072; i += 256) d[i] = a[i];
    }
    __syncthreads();
    int b = blockIdx.x >> 6;
    int n = ((blockIdx.x & 63) << 6) + (t & 63);
    int oh = t >> 6;

    float4 p4[16];
    const float* pb = points + (size_t)b * 64 * NN + n;
#pragma unroll
    for (int d4 = 0; d4 < 16; ++d4) {
        p4[d4].x = pb[(size_t)(4 * d4 + 0) * NN];
        p4[d4].y = pb[(size_t)(4 * d4 + 1) * NN];
        p4[d4].z = pb[(size_t)(4 * d4 + 2) * NN];
        p4[d4].w = pb[(size_t)(4 * d4 + 3) * NN];
    }
    float* outp = g_qkv + ((size_t)(b * NN + n)) * 192 + oh * 48;
    const float* swh = sw + oh * 48 * 64;
    for (int ob = 0; ob < 12; ++ob) {
        float a0 = 0.f, a1 = 0.f, a2 = 0.f, a3 = 0.f;
        const float4* w0 = (const float4*)(swh + (4 * ob + 0) * 64);
        const float4* w1 = (const float4*)(swh + (4 * ob + 1) * 64);
        const float4* w2 = (const float4*)(swh + (4 * ob + 2) * 64);
        const float4* w3 = (const float4*)(swh + (4 * ob + 3) * 64);
#pragma unroll
        for (int d4 = 0; d4 < 16; ++d4) {
            float4 pv = p4[d4];
            float4 wa = w0[d4], wb = w1[d4], wc = w2[d4], wd = w3[d4];
            a0 = fmaf(wa.x, pv.x, a0); a0 = fmaf(wa.y, pv.y, a0);
            a0 = fmaf(wa.z, pv.z, a0); a0 = fmaf(wa.w, pv.w, a0);
            a1 = fmaf(wb.x, pv.x, a1); a1 = fmaf(wb.y, pv.y, a1);
            a1 = fmaf(wb.z, pv.z, a1); a1 = fmaf(wb.w, pv.w, a1);
            a2 = fmaf(wc.x, pv.x, a2); a2 = fmaf(wc.y, pv.y, a2);
            a2 = fmaf(wc.z, pv.z, a2); a2 = fmaf(wc.w, pv.w, a2);
            a3 = fmaf(wd.x, pv.x, a3); a3 = fmaf(wd.y, pv.y, a3);
            a3 = fmaf(wd.z, pv.z, a3); a3 = fmaf(wd.w, pv.w, a3);
        }
        *(float4*)(outp + 4 * ob) = make_float4(a0, a1, a2, a3);
    }
}

// ---------------------------------------------------------------------------
// Kernel 2: KNN (unchanged)
// ---------------------------------------------------------------------------
__device__ __forceinline__ void topk_insert(float d2, int m, float bd[16], int bi[16]) {
    bd[15] = d2; bi[15] = m;
#pragma unroll
    for (int i = 15; i > 0; --i) {
        if (bd[i] < bd[i - 1]) {
            float td = bd[i]; bd[i] = bd[i - 1]; bd[i - 1] = td;
            int ti = bi[i]; bi[i] = bi[i - 1]; bi[i - 1] = ti;
        }
    }
}

__global__ void knn_kernel(const float* __restrict__ xyz) {
    extern __shared__ float sm[];
    float* cx = sm;
    float* cy = cx + NN;
    float* cz = cy + NN;
    float* csq = cz + NN;
    float* md = csq + NN;
    int* mi = (int*)(md + 256 * 16);

    int t = threadIdx.x;
    int b = blockIdx.x >> 6;
    int tile = blockIdx.x & 63;
    const float* xb = xyz + (size_t)b * 3 * NN;

    for (int m = t; m < NN; m += 256) {
        float x = xb[m], y = xb[NN + m], z = xb[2 * NN + m];
        cx[m] = x; cy[m] = y; cz[m] = z;
        csq[m] = x * x + y * y + z * z;
    }
    __syncthreads();

    int q = tile * 64 + (t >> 2);
    int p = t & 3;
    float qx = cx[q], qy = cy[q], qz = cz[q];
    float sqq = csq[q];

    float bd[16]; int bi[16];
#pragma unroll
    for (int i = 0; i < 16; ++i) { bd[i] = 3.4e38f; bi[i] = -1; }

    int m0 = p * 1024;
    for (int m = m0; m < m0 + 1024; m += 2) {
        float dot0 = fmaf(qx, cx[m], fmaf(qy, cy[m], qz * cz[m]));
        float dot1 = fmaf(qx, cx[m + 1], fmaf(qy, cy[m + 1], qz * cz[m + 1]));
        float d20 = fmaf(-2.f, dot0, sqq + csq[m]);
        float d21 = fmaf(-2.f, dot1, sqq + csq[m + 1]);
        if (d20 < bd[15]) topk_insert(d20, m, bd, bi);
        if (d21 < bd[15]) topk_insert(d21, m + 1, bd, bi);
    }
#pragma unroll
    for (int i = 0; i < 16; ++i) { md[t * 16 + i] = bd[i]; mi[t * 16 + i] = bi[i]; }
    __syncthreads();

    if (p == 0) {
        for (int src = 1; src < 4; ++src) {
            int base = (t + src) * 16;
            for (int e = 0; e < 16; ++e) {
                float d2 = md[base + e];
                if (d2 >= bd[15]) break;
                topk_insert(d2, mi[base + e], bd, bi);
            }
        }
        int* op = g_idx + ((size_t)(b * NN + q)) * KK;
#pragma unroll
        for (int i = 0; i < 16; ++i) op[i] = bi[i];
    }
}

// ---------------------------------------------------------------------------
// Kernel 3: pos-MLP -> g_pe (unchanged)
// ---------------------------------------------------------------------------
__global__ void __launch_bounds__(256, 2)
pos_kernel(const float* __restrict__ xyz,
           const float* __restrict__ w_pos1, const float* __restrict__ b_pos1,
           const float* __restrict__ w_pos2, const float* __restrict__ b_pos2) {
    extern __shared__ float sm[];
    float* swp2 = sm;
    float* swp1 = swp2 + 4096;
    float* sbp1 = swp1 + 192;
    float* sbp2 = sbp1 + 64;
    float* sph  = sbp2 + 64;

    int t = threadIdx.x;
    for (int i = t; i < 4096; i += 256) swp2[i] = w_pos2[i];
    if (t < 192) swp1[t] = w_pos1[t];
    if (t < 64) { sbp1[t] = b_pos1[t]; sbp2[t] = b_pos2[t]; }

    size_t gp0 = (size_t)blockIdx.x * 256;
    int b = (int)(gp0 >> 16);
    {
        size_t gp = gp0 + t;
        int n = (int)((gp >> 4) & 4095);
        int j = g_idx[gp];
        const float* xb = xyz + (size_t)b * 3 * NN;
        float gx0 = xb[n] - xb[j];
        float gx1 = xb[NN + n] - xb[NN + j];
        float gx2 = xb[2 * NN + n] - xb[2 * NN + j];
        __syncthreads();
#pragma unroll 8
        for (int h = 0; h < 64; ++h) {
            float v = fmaf(swp1[h * 3 + 0], gx0, sbp1[h]);
            v = fmaf(swp1[h * 3 + 1], gx1, v);
            v = fmaf(swp1[h * 3 + 2], gx2, v);
            sph[h * 256 + t] = fmaxf(v, 0.f);
        }
    }
    __syncthreads();

    int rg = t >> 5;
    int pg = t & 31;
    int o0 = rg * 8, p0 = pg * 8;
    float acc[8][8];
#pragma unroll
    for (int r = 0; r < 8; ++r)
#pragma unroll
        for (int c = 0; c < 8; ++c) acc[r][c] = sbp2[o0 + r];

    for (int k = 0; k < 64; k += 4) {
        float4 pa[4], pb[4];
#pragma unroll
        for (int kk = 0; kk < 4; ++kk) {
            pa[kk] = *(const float4*)(sph + (k + kk) * 256 + p0);
            pb[kk] = *(const float4*)(sph + (k + kk) * 256 + p0 + 4);
        }
#pragma unroll
        for (int r = 0; r < 8; ++r) {
            float4 w = *(const float4*)(swp2 + (o0 + r) * 64 + k);
#pragma unroll
            for (int c = 0; c < 4; ++c) {
                acc[r][c] = fmaf(w.x, ((const float*)&pa[0])[c], acc[r][c]);
                acc[r][c] = fmaf(w.y, ((const float*)&pa[1])[c], acc[r][c]);
                acc[r][c] = fmaf(w.z, ((const float*)&pa[2])[c], acc[r][c]);
                acc[r][c] = fmaf(w.w, ((const float*)&pa[3])[c], acc[r][c]);
                acc[r][c + 4] = fmaf(w.x, ((const float*)&pb[0])[c], acc[r][c + 4]);
                acc[r][c + 4] = fmaf(w.y, ((const float*)&pb[1])[c], acc[r][c + 4]);
                acc[r][c + 4] = fmaf(w.z, ((const float*)&pb[2])[c], acc[r][c + 4]);
                acc[r][c + 4] = fmaf(w.w, ((const float*)&pb[3])[c], acc[r][c + 4]);
            }
        }
    }
#pragma unroll
    for (int i = 0; i < 8; ++i) {
        float* dst = g_pe + (gp0 + p0 + i) * 64 + o0;
        *(float4*)(dst)     = make_float4(acc[0][i], acc[1][i], acc[2][i], acc[3][i]);
        *(float4*)(dst + 4) = make_float4(acc[4][i], acc[5][i], acc[6][i], acc[7][i]);
    }
}

// ---------------------------------------------------------------------------
// Kernel 4: fused att-MLP via mma.sync (bf16 hi/lo 3-pass).
// 512 threads = 16 warps; 2 tiles x 8 queries (128 neighbor-cols) per block.
// E: [128c x 256r x 64k] in 2 r-phases; F: [128c x 64o x 256k] split-K over
// the same phases with register-resident accumulators.
// ---------------------------------------------------------------------------
__global__ void __launch_bounds__(512, 1)
fused_mma_kernel(const float* __restrict__ w_att1, const float* __restrict__ b_att1,
                 const float* __restrict__ w_att2, const float* __restrict__ b_att2,
                 float* __restrict__ out) {
    extern __shared__ char smem[];
    uint sbase = smem_u32(smem);
    int t = threadIdx.x, wid = t >> 5, lane = t & 31;
    float* sb1 = (float*)(smem + OFF_B1);
    float* sb2 = (float*)(smem + OFF_B2);
    int* sj = (int*)(smem + OFF_SJ);

    // ---- prologue: weights -> bf16 hi/lo swizzled smem ----
    for (int i = t; i < 4096; i += 512) {       // w1 [256][64]
        float4 f = ((const float4*)w_att1)[i];
        int r = i >> 4, k = (i * 4) & 63;
        int l = k * 2;
        int swl = (l ^ ((r & 7) << 4));
        *(uint*)(smem + OFF_W1H + r * 128 + swl)     = bf2(f.x, f.y);
        *(uint*)(smem + OFF_W1H + r * 128 + swl + 4) = bf2(f.z, f.w);
        *(uint*)(smem + OFF_W1L + r * 128 + swl)     = bf2(bfres(f.x), bfres(f.y));
        *(uint*)(smem + OFF_W1L + r * 128 + swl + 4) = bf2(bfres(f.z), bfres(f.w));
    }
    for (int i = t; i < 4096; i += 512) {       // w2 [64][256]
        float4 f = ((const float4*)w_att2)[i];
        int o = i >> 6, k = (i * 4) & 255;
        int l = k * 2;
        int swl = (l ^ ((o & 7) << 4));
        *(uint*)(smem + OFF_W2H + o * 512 + swl)     = bf2(f.x, f.y);
        *(uint*)(smem + OFF_W2H + o * 512 + swl + 4) = bf2(f.z, f.w);
        *(uint*)(smem + OFF_W2L + o * 512 + swl)     = bf2(bfres(f.x), bfres(f.y));
        *(uint*)(smem + OFF_W2L + o * 512 + swl + 4) = bf2(bfres(f.z), bfres(f.w));
    }
    if (t < 256) sb1[t] = b_att1[t];
    if (t < 64) sb2[t] = b_att2[t];

    int b = blockIdx.x >> 8;
    int nb = (blockIdx.x & 255) << 4;
    const int c0 = (wid & 3) * 32;      // warp's neighbor-column range
    const int r0w = (wid >> 2) * 32;    // E: r-range within phase-half
    const int o0 = (wid >> 2) * 16;     // F: o-range

    for (int tile = 0; tile < 2; ++tile) {
        int n0 = nb + tile * 8;
        __syncthreads();  // prologue done / prev tile fully consumed

        // ---- gather: x = q - k + pe -> XH/XL [128 c][64 d] bf16 swz ----
        {
            int c = t >> 2;
            int dq = (t & 3) << 4;
            int qi = c >> 4;
            int j = g_idx[((size_t)(b * NN + n0 + qi)) * KK + (c & 15)];
            if ((t & 3) == 0) sj[c] = j;
            const float* kp = g_qkv + ((size_t)(b * NN + j)) * 192 + 64 + dq;
            const float* qp = g_qkv + ((size_t)(b * NN + n0 + qi)) * 192 + dq;
            const float* pp = g_pe + ((size_t)b * 65536 + (size_t)n0 * 16 + c) * 64 + dq;
            int rowb = c * 128;
            int sx = (c & 7) << 4;
#pragma unroll
            for (int i = 0; i < 4; ++i) {
                float4 kk = *(const float4*)(kp + 4 * i);
                float4 qq = *(const float4*)(qp + 4 * i);
                float4 pe = *(const float4*)(pp + 4 * i);
                float x0 = qq.x - kk.x + pe.x;
                float x1 = qq.y - kk.y + pe.y;
                float x2 = qq.z - kk.z + pe.z;
                float x3 = qq.w - kk.w + pe.w;
                int l = (dq + 4 * i) * 2;
                int swl = l ^ sx;
                *(uint*)(smem + OFF_XH + rowb + swl)     = bf2(x0, x1);
                *(uint*)(smem + OFF_XH + rowb + swl + 4) = bf2(x2, x3);
                *(uint*)(smem + OFF_XL + rowb + swl)     = bf2(bfres(x0), bfres(x1));
                *(uint*)(smem + OFF_XL + rowb + swl + 4) = bf2(bfres(x2), bfres(x3));
            }
        }
        __syncthreads();

        float dF[2][2][4];
#pragma unroll
        for (int mt = 0; mt < 2; ++mt)
#pragma unroll
            for (int nt = 0; nt < 2; ++nt)
#pragma unroll
                for (int e = 0; e < 4; ++e) dF[mt][nt][e] = 0.f;

        for (int ph = 0; ph < 2; ++ph) {
            // ---- E: h-half = relu(x @ w1^T + b1), 3 bf16 passes ----
            float dE[2][4][4];
#pragma unroll
            for (int mt = 0; mt < 2; ++mt)
#pragma unroll
                for (int nt = 0; nt < 4; ++nt)
#pragma unroll
                    for (int e = 0; e < 4; ++e) dE[mt][nt][e] = 0.f;

            int nbse = ph * 128 + r0w;
#pragma unroll
            for (int ks = 0; ks < 4; ++ks) {
                int L0 = ks * 32;
                uint aH[2][4], aL[2][4], bH[2][4], bL[2][4];
                ldsm4(aH[0], afrag_addr(sbase + OFF_XH, 128, c0, L0, lane));
                ldsm4(aH[1], afrag_addr(sbase + OFF_XH, 128, c0 + 16, L0, lane));
                ldsm4(aL[0], afrag_addr(sbase + OFF_XL, 128, c0, L0, lane));
                ldsm4(aL[1], afrag_addr(sbase + OFF_XL, 128, c0 + 16, L0, lane));
                ldsm4(bH[0], bfrag_addr(sbase + OFF_W1H, 128, nbse, L0, lane));
                ldsm4(bH[1], bfrag_addr(sbase + OFF_W1H, 128, nbse + 16, L0, lane));
                ldsm4(bL[0], bfrag_addr(sbase + OFF_W1L, 128, nbse, L0, lane));
                ldsm4(bL[1], bfrag_addr(sbase + OFF_W1L, 128, nbse + 16, L0, lane));
#pragma unroll
                for (int mt = 0; mt < 2; ++mt)
#pragma unroll
                    for (int nt = 0; nt < 4; ++nt) {
                        const uint* bh = &bH[nt >> 1][(nt & 1) * 2];
                        const uint* bl = &bL[nt >> 1][(nt & 1) * 2];
                        mma_bf16(dE[mt][nt], aH[mt], bh);
                        mma_bf16(dE[mt][nt], aH[mt], bl);
                        mma_bf16(dE[mt][nt], aL[mt], bh);
                    }
            }
            // epilogue: relu + bias -> HH/HL (k = phase-local r)
#pragma unroll
            for (int mt = 0; mt < 2; ++mt) {
                int cA = c0 + mt * 16 + (lane >> 2);
                int cB = cA + 8;
#pragma unroll
                for (int nt = 0; nt < 4; ++nt) {
                    int rl = r0w + nt * 8 + (lane & 3) * 2;
                    int rg = ph * 128 + rl;
                    float b0v = sb1[rg], b1v = sb1[rg + 1];
                    float v0 = fmaxf(dE[mt][nt][0] + b0v, 0.f);
                    float v1 = fmaxf(dE[mt][nt][1] + b1v, 0.f);
                    float v2 = fmaxf(dE[mt][nt][2] + b0v, 0.f);
                    float v3 = fmaxf(dE[mt][nt][3] + b1v, 0.f);
                    int lA = (rl * 2) ^ ((cA & 7) << 4);
                    int lB = (rl * 2) ^ ((cB & 7) << 4);
                    *(uint*)(smem + OFF_HH + cA * 256 + lA) = bf2(v0, v1);
                    *(uint*)(smem + OFF_HL + cA * 256 + lA) = bf2(bfres(v0), bfres(v1));
                    *(uint*)(smem + OFF_HH + cB * 256 + lB) = bf2(v2, v3);
                    *(uint*)(smem + OFF_HL + cB * 256 + lB) = bf2(bfres(v2), bfres(v3));
                }
            }
            __syncthreads();  // H visible to all warps

            // ---- F: sim += h-half @ w2-half^T, 3 bf16 passes ----
#pragma unroll
            for (int ks = 0; ks < 8; ++ks) {
                int L0 = ks * 32;
                int L0w = ph * 256 + L0;
                uint aH[2][4], aL[2][4], bH[4], bL[4];
                ldsm4(aH[0], afrag_addr(sbase + OFF_HH, 256, c0, L0, lane));
                ldsm4(aH[1], afrag_addr(sbase + OFF_HH, 256, c0 + 16, L0, lane));
                ldsm4(aL[0], afrag_addr(sbase + OFF_HL, 256, c0, L0, lane));
                ldsm4(aL[1], afrag_addr(sbase + OFF_HL, 256, c0 + 16, L0, lane));
                ldsm4(bH, bfrag_addr(sbase + OFF_W2H, 512, o0, L0w, lane));
                ldsm4(bL, bfrag_addr(sbase + OFF_W2L, 512, o0, L0w, lane));
#pragma unroll
                for (int mt = 0; mt < 2; ++mt)
#pragma unroll
                    for (int nt = 0; nt < 2; ++nt) {
                        const uint* bh = &bH[nt * 2];
                        const uint* bl = &bL[nt * 2];
                        mma_bf16(dF[mt][nt], aH[mt], bh);
                        mma_bf16(dF[mt][nt], aH[mt], bl);
                        mma_bf16(dF[mt][nt], aL[mt], bh);
                    }
            }
            __syncthreads();  // all F reads of H done before next phase/sim
        }

        // ---- sim = dF + b2 -> smem [128 c][68] fp32 (reuses H region) ----
        {
            float* simf = (float*)(smem + OFF_SIM);
#pragma unroll
            for (int mt = 0; mt < 2; ++mt) {
                int cA = c0 + mt * 16 + (lane >> 2);
                int cB = cA + 8;
#pragma unroll
                for (int nt = 0; nt < 2; ++nt) {
                    int o = o0 + nt * 8 + (lane & 3) * 2;
                    float b0v = sb2[o], b1v = sb2[o + 1];
                    simf[cA * 68 + o]     = dF[mt][nt][0] + b0v;
                    simf[cA * 68 + o + 1] = dF[mt][nt][1] + b1v;
                    simf[cB * 68 + o]     = dF[mt][nt][2] + b0v;
                    simf[cB * 68 + o + 1] = dF[mt][nt][3] + b1v;
                }
            }
        }
        __syncthreads();

        // ---- softmax over K + aggregation (v re-gathered from L2) ----
        {
            int o = t >> 3, q = t & 7;
            const float* sp = (const float*)(smem + OFF_SIM) + (q * 16) * 68 + o;
            float mx = -3.4e38f;
#pragma unroll
            for (int k = 0; k < 16; ++k) mx = fmaxf(mx, sp[k * 68]);
            float vg[16];
#pragma unroll
            for (int k = 0; k < 16; ++k) {
                int j = sj[q * 16 + k];
                vg[k] = __ldg(g_qkv + ((size_t)(b * NN + j)) * 192 + 128 + o)
                      + __ldg(g_pe + ((size_t)b * 65536 + (size_t)n0 * 16 + q * 16 + k) * 64 + o);
            }
            float s = 0.f, a = 0.f;
#pragma unroll
            for (int k = 0; k < 16; ++k) {
                float e = __expf(sp[k * 68] - mx);
                s += e;
                a = fmaf(e, vg[k], a);
            }
            out[((size_t)(b * 64 + o)) * NN + n0 + q] = a / s;
        }
    }
}

// ---------------------------------------------------------------------------
extern "C" void kernel_launch(void* const* d_in, const int* in_sizes, int n_in,
                              void* d_out, int out_size) {
    (void)in_sizes; (void)n_in; (void)out_size;
    const float* xyz    = (const float*)d_in[0];
    const float* points = (const float*)d_in[1];
    const float* w_qkv  = (const float*)d_in[2];
    const float* w_pos1 = (const float*)d_in[3];
    const float* b_pos1 = (const float*)d_in[4];
    const float* w_pos2 = (const float*)d_in[5];
    const float* b_pos2 = (const float*)d_in[6];
    const float* w_att1 = (const float*)d_in[7];
    const float* b_att1 = (const float*)d_in[8];
    const float* w_att2 = (const float*)d_in[9];
    const float* b_att2 = (const float*)d_in[10];
    float* out = (float*)d_out;

    cudaFuncSetAttribute(qkv_kernel, cudaFuncAttributeMaxDynamicSharedMemorySize, 49152);
    cudaFuncSetAttribute(knn_kernel, cudaFuncAttributeMaxDynamicSharedMemorySize, 98304);
    cudaFuncSetAttribute(pos_kernel, cudaFuncAttributeMaxDynamicSharedMemorySize, 83200);
    cudaFuncSetAttribute(fused_mma_kernel, cudaFuncAttributeMaxDynamicSharedMemorySize, SMEM_TC);

    qkv_kernel<<<BB * (NN / 64), 256, 49152>>>(points, w_qkv);
    knn_kernel<<<BB * (NN / 64), 256, 98304>>>(xyz);
    pos_kernel<<<BB * NN * KK / 256, 256, 83200>>>(xyz, w_pos1, b_pos1, w_pos2, b_pos2);
    fused_mma_kernel<<<BB * (NN / 16), 512, SMEM_TC>>>(w_att1, b_att1, w_att2, b_att2, out);
}

// round 8
// speedup vs baseline: 2.3656x; 1.0749x over previous
#include <cuda_runtime.h>
#include <cuda_bf16.h>
#include <math.h>

#define BB 4
#define NN 4096
#define KK 16

typedef unsigned long long ull;
typedef unsigned int uint;

// scratch (device globals: allocation-free per harness rules)
__device__ float g_qkv[BB * NN * 192];            // point-major: [b][n][192]
__device__ int   g_idx[BB * NN * KK];             // [b][n][k]
__device__ float g_pe[(size_t)BB * NN * KK * 64]; // [gp][64]

// ============================ mma.sync helpers =============================
__device__ __forceinline__ uint smem_u32(const void* p) {
    uint a;
    asm("{ .reg .u64 t; cvta.to.shared.u64 t, %1; cvt.u32.u64 %0, t; }"
        : "=r"(a) : "l"(p));
    return a;
}
__device__ __forceinline__ void ldsm4(uint* r, uint addr) {
    asm volatile("ldmatrix.sync.aligned.m8n8.x4.shared.b16 {%0,%1,%2,%3}, [%4];"
                 : "=r"(r[0]), "=r"(r[1]), "=r"(r[2]), "=r"(r[3]) : "r"(addr));
}
__device__ __forceinline__ void mma_bf16(float* d, const uint* a, const uint* b) {
    asm volatile(
        "mma.sync.aligned.m16n8k16.row.col.f32.bf16.bf16.f32 "
        "{%0,%1,%2,%3},{%4,%5,%6,%7},{%8,%9},{%0,%1,%2,%3};"
        : "+f"(d[0]), "+f"(d[1]), "+f"(d[2]), "+f"(d[3])
        : "r"(a[0]), "r"(a[1]), "r"(a[2]), "r"(a[3]), "r"(b[0]), "r"(b[1]));
}
__device__ __forceinline__ uint bf2(float a, float b) {
    unsigned short ha = __bfloat16_as_ushort(__float2bfloat16_rn(a));
    unsigned short hb = __bfloat16_as_ushort(__float2bfloat16_rn(b));
    return (uint)ha | ((uint)hb << 16);
}
__device__ __forceinline__ float bfres(float a) {
    return a - __bfloat162float(__float2bfloat16_rn(a));
}
// A-fragment ldmatrix.x4 address (16x16 tile at (row0, byte L0), row width W)
__device__ __forceinline__ uint afrag_addr(uint base, int W, int row0, int L0, int lane) {
    int row = row0 + (lane & 7) + ((lane >> 3) & 1) * 8;
    int l = L0 + (lane >> 4) * 16;
    return base + row * W + (l ^ ((row & 7) << 4));
}
// B-fragment ldmatrix.x4 address (two n-tiles n0..n0+15, k16 at byte L0)
__device__ __forceinline__ uint bfrag_addr(uint base, int W, int n0, int L0, int lane) {
    int row = n0 + (lane & 7) + (lane >> 4) * 8;
    int l = L0 + ((lane >> 3) & 1) * 16;
    return base + row * W + (l ^ ((row & 7) << 4));
}

// fused kernel smem byte offsets
#define OFF_W1H 0u        /* [256 r][64 k] bf16 swz, 32768 */
#define OFF_W1L 32768u
#define OFF_W2H 65536u    /* [64 o][256 k] bf16 swz, 32768 */
#define OFF_W2L 98304u
#define OFF_XH  131072u   /* [128 c][64 d] bf16 swz, 16384 */
#define OFF_XL  147456u
#define OFF_HH  163840u   /* [128 c][128 r-half] bf16 swz, 32768 */
#define OFF_HL  196608u
#define OFF_SIM 163840u   /* reuse H: sim [128][68] fp32 = 34816 */
#define OFF_B1  229376u
#define OFF_B2  230400u
#define OFF_SJ  230656u   /* int[128] */
#define SMEM_TC 231168u

// pos kernel smem byte offsets
#define POFF_AH  0u       /* ph hi [256 p][64 h] bf16 swz, 32768 */
#define POFF_AL  32768u
#define POFF_WH  65536u   /* w_pos2 hi [64 o][64 h] bf16 swz, 8192 */
#define POFF_WL  73728u
#define POFF_WP1 81920u   /* fp32 192 */
#define POFF_BP1 82688u   /* fp32 64 */
#define POFF_BP2 82944u   /* fp32 64 */
#define SMEM_POS 83200u

// ---------------------------------------------------------------------------
// Kernel 1: qkv (unchanged)
// ---------------------------------------------------------------------------
__global__ void qkv_kernel(const float* __restrict__ points,
                           const float* __restrict__ w_qkv) {
    extern __shared__ float sw[];
    int t = threadIdx.x;
    {
        const float4* a = (const float4*)w_qkv;
        float4* d = (float4*)sw;
        for (int i = t; i < 3072; i += 256) d[i] = a[i];
    }
    __syncthreads();
    int b = blockIdx.x >> 6;
    int n = ((blockIdx.x & 63) << 6) + (t & 63);
    int oh = t >> 6;

    float4 p4[16];
    const float* pb = points + (size_t)b * 64 * NN + n;
#pragma unroll
    for (int d4 = 0; d4 < 16; ++d4) {
        p4[d4].x = pb[(size_t)(4 * d4 + 0) * NN];
        p4[d4].y = pb[(size_t)(4 * d4 + 1) * NN];
        p4[d4].z = pb[(size_t)(4 * d4 + 2) * NN];
        p4[d4].w = pb[(size_t)(4 * d4 + 3) * NN];
    }
    float* outp = g_qkv + ((size_t)(b * NN + n)) * 192 + oh * 48;
    const float* swh = sw + oh * 48 * 64;
    for (int ob = 0; ob < 12; ++ob) {
        float a0 = 0.f, a1 = 0.f, a2 = 0.f, a3 = 0.f;
        const float4* w0 = (const float4*)(swh + (4 * ob + 0) * 64);
        const float4* w1 = (const float4*)(swh + (4 * ob + 1) * 64);
        const float4* w2 = (const float4*)(swh + (4 * ob + 2) * 64);
        const float4* w3 = (const float4*)(swh + (4 * ob + 3) * 64);
#pragma unroll
        for (int d4 = 0; d4 < 16; ++d4) {
            float4 pv = p4[d4];
            float4 wa = w0[d4], wb = w1[d4], wc = w2[d4], wd = w3[d4];
            a0 = fmaf(wa.x, pv.x, a0); a0 = fmaf(wa.y, pv.y, a0);
            a0 = fmaf(wa.z, pv.z, a0); a0 = fmaf(wa.w, pv.w, a0);
            a1 = fmaf(wb.x, pv.x, a1); a1 = fmaf(wb.y, pv.y, a1);
            a1 = fmaf(wb.z, pv.z, a1); a1 = fmaf(wb.w, pv.w, a1);
            a2 = fmaf(wc.x, pv.x, a2); a2 = fmaf(wc.y, pv.y, a2);
            a2 = fmaf(wc.z, pv.z, a2); a2 = fmaf(wc.w, pv.w, a2);
            a3 = fmaf(wd.x, pv.x, a3); a3 = fmaf(wd.y, pv.y, a3);
            a3 = fmaf(wd.z, pv.z, a3); a3 = fmaf(wd.w, pv.w, a3);
        }
        *(float4*)(outp + 4 * ob) = make_float4(a0, a1, a2, a3);
    }
}

// ---------------------------------------------------------------------------
// Kernel 2: KNN — float4-packed candidates (1 LDS.128/candidate).
// Identical FP expression order to preserve values and tie order.
// ---------------------------------------------------------------------------
__device__ __forceinline__ void topk_insert(float d2, int m, float bd[16], int bi[16]) {
    bd[15] = d2; bi[15] = m;
#pragma unroll
    for (int i = 15; i > 0; --i) {
        if (bd[i] < bd[i - 1]) {
            float td = bd[i]; bd[i] = bd[i - 1]; bd[i - 1] = td;
            int ti = bi[i]; bi[i] = bi[i - 1]; bi[i - 1] = ti;
        }
    }
}

__global__ void knn_kernel(const float* __restrict__ xyz) {
    extern __shared__ float sm[];
    float4* c4 = (float4*)sm;          // 4096 float4 = 65536 B
    float* md = sm + 16384;            // 256*16 floats
    int* mi = (int*)(md + 4096);       // 256*16 ints

    int t = threadIdx.x;
    int b = blockIdx.x >> 6;
    int tile = blockIdx.x & 63;
    const float* xb = xyz + (size_t)b * 3 * NN;

    for (int m = t; m < NN; m += 256) {
        float x = xb[m], y = xb[NN + m], z = xb[2 * NN + m];
        c4[m] = make_float4(x, y, z, x * x + y * y + z * z);
    }
    __syncthreads();

    int q = tile * 64 + (t >> 2);
    int p = t & 3;
    float4 qc = c4[q];
    float qx = qc.x, qy = qc.y, qz = qc.z, sqq = qc.w;

    float bd[16]; int bi[16];
#pragma unroll
    for (int i = 0; i < 16; ++i) { bd[i] = 3.4e38f; bi[i] = -1; }

    int m0 = p * 1024;
    for (int m = m0; m < m0 + 1024; m += 2) {
        float4 ca = c4[m], cb = c4[m + 1];
        float dot0 = fmaf(qx, ca.x, fmaf(qy, ca.y, qz * ca.z));
        float dot1 = fmaf(qx, cb.x, fmaf(qy, cb.y, qz * cb.z));
        float d20 = fmaf(-2.f, dot0, sqq + ca.w);
        float d21 = fmaf(-2.f, dot1, sqq + cb.w);
        if (d20 < bd[15]) topk_insert(d20, m, bd, bi);
        if (d21 < bd[15]) topk_insert(d21, m + 1, bd, bi);
    }
#pragma unroll
    for (int i = 0; i < 16; ++i) { md[t * 16 + i] = bd[i]; mi[t * 16 + i] = bi[i]; }
    __syncthreads();

    if (p == 0) {
        for (int src = 1; src < 4; ++src) {
            int base = (t + src) * 16;
            for (int e = 0; e < 16; ++e) {
                float d2 = md[base + e];
                if (d2 >= bd[15]) break;
                topk_insert(d2, mi[base + e], bd, bi);
            }
        }
        int* op = g_idx + ((size_t)(b * NN + q)) * KK;
#pragma unroll
        for (int i = 0; i < 16; ++i) op[i] = bi[i];
    }
}

// ---------------------------------------------------------------------------
// Kernel 3: pos-MLP -> g_pe. Layer 1 scalar; layer 2 via mma.sync bf16 hi/lo
// 3-pass (same verified fragment mapping as the fused kernel).
// 256 threads = 8 warps; 256 pairs/block; D[256 p][64 o].
// ---------------------------------------------------------------------------
__global__ void __launch_bounds__(256, 2)
pos_kernel(const float* __restrict__ xyz,
           const float* __restrict__ w_pos1, const float* __restrict__ b_pos1,
           const float* __restrict__ w_pos2, const float* __restrict__ b_pos2) {
    extern __shared__ char psm[];
    uint sbase = smem_u32(psm);
    int t = threadIdx.x, wid = t >> 5, lane = t & 31;
    float* wp1 = (float*)(psm + POFF_WP1);
    float* bp1 = (float*)(psm + POFF_BP1);
    float* bp2 = (float*)(psm + POFF_BP2);

    // w_pos2 [64 o][64 h] -> bf16 hi/lo swizzled
    for (int i = t; i < 1024; i += 256) {
        float4 f = ((const float4*)w_pos2)[i];
        int o = i >> 4, h = (i * 4) & 63;
        int swl = (h * 2) ^ ((o & 7) << 4);
        *(uint*)(psm + POFF_WH + o * 128 + swl)     = bf2(f.x, f.y);
        *(uint*)(psm + POFF_WH + o * 128 + swl + 4) = bf2(f.z, f.w);
        *(uint*)(psm + POFF_WL + o * 128 + swl)     = bf2(bfres(f.x), bfres(f.y));
        *(uint*)(psm + POFF_WL + o * 128 + swl + 4) = bf2(bfres(f.z), bfres(f.w));
    }
    if (t < 192) wp1[t] = w_pos1[t];
    if (t < 64) { bp1[t] = b_pos1[t]; bp2[t] = b_pos2[t]; }

    size_t gp0 = (size_t)blockIdx.x * 256;
    int b = (int)(gp0 >> 16);

    // layer 1: one pair per thread -> ph row (bf16 hi/lo, swizzled)
    {
        size_t gp = gp0 + t;
        int n = (int)((gp >> 4) & 4095);
        int j = g_idx[gp];
        const float* xb = xyz + (size_t)b * 3 * NN;
        float gx0 = xb[n] - xb[j];
        float gx1 = xb[NN + n] - xb[NN + j];
        float gx2 = xb[2 * NN + n] - xb[2 * NN + j];
        __syncthreads();  // wp1/bp1 visible
        int rowb = t * 128;
        int sx = (t & 7) << 4;
#pragma unroll
        for (int h = 0; h < 64; h += 2) {
            float v0 = fmaf(wp1[h * 3 + 2], gx2,
                       fmaf(wp1[h * 3 + 1], gx1,
                       fmaf(wp1[h * 3 + 0], gx0, bp1[h])));
            float v1 = fmaf(wp1[h * 3 + 5], gx2,
                       fmaf(wp1[h * 3 + 4], gx1,
                       fmaf(wp1[h * 3 + 3], gx0, bp1[h + 1])));
            v0 = fmaxf(v0, 0.f); v1 = fmaxf(v1, 0.f);
            int swl = (h * 2) ^ sx;
            *(uint*)(psm + POFF_AH + rowb + swl) = bf2(v0, v1);
            *(uint*)(psm + POFF_AL + rowb + swl) = bf2(bfres(v0), bfres(v1));
        }
    }
    __syncthreads();

    // layer 2 MMA: pe[256 p][64 o] = ph @ w_pos2^T (K=64), 3 bf16 passes
    {
        int p0 = wid * 32;
        float d[2][8][4];
#pragma unroll
        for (int mt = 0; mt < 2; ++mt)
#pragma unroll
            for (int nt = 0; nt < 8; ++nt)
#pragma unroll
                for (int e = 0; e < 4; ++e) d[mt][nt][e] = 0.f;

#pragma unroll
        for (int ks = 0; ks < 4; ++ks) {
            int L0 = ks * 32;
            uint aH[2][4], aL[2][4], bH[4][4], bL[4][4];
            ldsm4(aH[0], afrag_addr(sbase + POFF_AH, 128, p0, L0, lane));
            ldsm4(aH[1], afrag_addr(sbase + POFF_AH, 128, p0 + 16, L0, lane));
            ldsm4(aL[0], afrag_addr(sbase + POFF_AL, 128, p0, L0, lane));
            ldsm4(aL[1], afrag_addr(sbase + POFF_AL, 128, p0 + 16, L0, lane));
#pragma unroll
            for (int g = 0; g < 4; ++g) {
                ldsm4(bH[g], bfrag_addr(sbase + POFF_WH, 128, g * 16, L0, lane));
                ldsm4(bL[g], bfrag_addr(sbase + POFF_WL, 128, g * 16, L0, lane));
            }
#pragma unroll
            for (int mt = 0; mt < 2; ++mt)
#pragma unroll
                for (int nt = 0; nt < 8; ++nt) {
                    const uint* bh = &bH[nt >> 1][(nt & 1) * 2];
                    const uint* bl = &bL[nt >> 1][(nt & 1) * 2];
                    mma_bf16(d[mt][nt], aH[mt], bh);
                    mma_bf16(d[mt][nt], aH[mt], bl);
                    mma_bf16(d[mt][nt], aL[mt], bh);
                }
        }
        // epilogue: + b_pos2 -> g_pe (float2 stores, coalesced within rows)
#pragma unroll
        for (int mt = 0; mt < 2; ++mt) {
            int cA = p0 + mt * 16 + (lane >> 2);
            int cB = cA + 8;
#pragma unroll
            for (int nt = 0; nt < 8; ++nt) {
                int o = nt * 8 + (lane & 3) * 2;
                float b0v = bp2[o], b1v = bp2[o + 1];
                *(float2*)(g_pe + (gp0 + cA) * 64 + o) =
                    make_float2(d[mt][nt][0] + b0v, d[mt][nt][1] + b1v);
                *(float2*)(g_pe + (gp0 + cB) * 64 + o) =
                    make_float2(d[mt][nt][2] + b0v, d[mt][nt][3] + b1v);
            }
        }
    }
}

// ---------------------------------------------------------------------------
// Kernel 4: fused att-MLP via mma.sync (unchanged from R7 — verified).
// ---------------------------------------------------------------------------
__global__ void __launch_bounds__(512, 1)
fused_mma_kernel(const float* __restrict__ w_att1, const float* __restrict__ b_att1,
                 const float* __restrict__ w_att2, const float* __restrict__ b_att2,
                 float* __restrict__ out) {
    extern __shared__ char smem[];
    uint sbase = smem_u32(smem);
    int t = threadIdx.x, wid = t >> 5, lane = t & 31;
    float* sb1 = (float*)(smem + OFF_B1);
    float* sb2 = (float*)(smem + OFF_B2);
    int* sj = (int*)(smem + OFF_SJ);

    for (int i = t; i < 4096; i += 512) {       // w1 [256][64]
        float4 f = ((const float4*)w_att1)[i];
        int r = i >> 4, k = (i * 4) & 63;
        int swl = ((k * 2) ^ ((r & 7) << 4));
        *(uint*)(smem + OFF_W1H + r * 128 + swl)     = bf2(f.x, f.y);
        *(uint*)(smem + OFF_W1H + r * 128 + swl + 4) = bf2(f.z, f.w);
        *(uint*)(smem + OFF_W1L + r * 128 + swl)     = bf2(bfres(f.x), bfres(f.y));
        *(uint*)(smem + OFF_W1L + r * 128 + swl + 4) = bf2(bfres(f.z), bfres(f.w));
    }
    for (int i = t; i < 4096; i += 512) {       // w2 [64][256]
        float4 f = ((const float4*)w_att2)[i];
        int o = i >> 6, k = (i * 4) & 255;
        int swl = ((k * 2) ^ ((o & 7) << 4));
        *(uint*)(smem + OFF_W2H + o * 512 + swl)     = bf2(f.x, f.y);
        *(uint*)(smem + OFF_W2H + o * 512 + swl + 4) = bf2(f.z, f.w);
        *(uint*)(smem + OFF_W2L + o * 512 + swl)     = bf2(bfres(f.x), bfres(f.y));
        *(uint*)(smem + OFF_W2L + o * 512 + swl + 4) = bf2(bfres(f.z), bfres(f.w));
    }
    if (t < 256) sb1[t] = b_att1[t];
    if (t < 64) sb2[t] = b_att2[t];

    int b = blockIdx.x >> 8;
    int nb = (blockIdx.x & 255) << 4;
    const int c0 = (wid & 3) * 32;
    const int r0w = (wid >> 2) * 32;
    const int o0 = (wid >> 2) * 16;

    for (int tile = 0; tile < 2; ++tile) {
        int n0 = nb + tile * 8;
        __syncthreads();

        {
            int c = t >> 2;
            int dq = (t & 3) << 4;
            int qi = c >> 4;
            int j = g_idx[((size_t)(b * NN + n0 + qi)) * KK + (c & 15)];
            if ((t & 3) == 0) sj[c] = j;
            const float* kp = g_qkv + ((size_t)(b * NN + j)) * 192 + 64 + dq;
            const float* qp = g_qkv + ((size_t)(b * NN + n0 + qi)) * 192 + dq;
            const float* pp = g_pe + ((size_t)b * 65536 + (size_t)n0 * 16 + c) * 64 + dq;
            int rowb = c * 128;
            int sx = (c & 7) << 4;
#pragma unroll
            for (int i = 0; i < 4; ++i) {
                float4 kk = *(const float4*)(kp + 4 * i);
                float4 qq = *(const float4*)(qp + 4 * i);
                float4 pe = *(const float4*)(pp + 4 * i);
                float x0 = qq.x - kk.x + pe.x;
                float x1 = qq.y - kk.y + pe.y;
                float x2 = qq.z - kk.z + pe.z;
                float x3 = qq.w - kk.w + pe.w;
                int swl = ((dq + 4 * i) * 2) ^ sx;
                *(uint*)(smem + OFF_XH + rowb + swl)     = bf2(x0, x1);
                *(uint*)(smem + OFF_XH + rowb + swl + 4) = bf2(x2, x3);
                *(uint*)(smem + OFF_XL + rowb + swl)     = bf2(bfres(x0), bfres(x1));
                *(uint*)(smem + OFF_XL + rowb + swl + 4) = bf2(bfres(x2), bfres(x3));
            }
        }
        __syncthreads();

        float dF[2][2][4];
#pragma unroll
        for (int mt = 0; mt < 2; ++mt)
#pragma unroll
            for (int nt = 0; nt < 2; ++nt)
#pragma unroll
                for (int e = 0; e < 4; ++e) dF[mt][nt][e] = 0.f;

        for (int ph = 0; ph < 2; ++ph) {
            float dE[2][4][4];
#pragma unroll
            for (int mt = 0; mt < 2; ++mt)
#pragma unroll
                for (int nt = 0; nt < 4; ++nt)
#pragma unroll
                    for (int e = 0; e < 4; ++e) dE[mt][nt][e] = 0.f;

            int nbse = ph * 128 + r0w;
#pragma unroll
            for (int ks = 0; ks < 4; ++ks) {
                int L0 = ks * 32;
                uint aH[2][4], aL[2][4], bH[2][4], bL[2][4];
                ldsm4(aH[0], afrag_addr(sbase + OFF_XH, 128, c0, L0, lane));
                ldsm4(aH[1], afrag_addr(sbase + OFF_XH, 128, c0 + 16, L0, lane));
                ldsm4(aL[0], afrag_addr(sbase + OFF_XL, 128, c0, L0, lane));
                ldsm4(aL[1], afrag_addr(sbase + OFF_XL, 128, c0 + 16, L0, lane));
                ldsm4(bH[0], bfrag_addr(sbase + OFF_W1H, 128, nbse, L0, lane));
                ldsm4(bH[1], bfrag_addr(sbase + OFF_W1H, 128, nbse + 16, L0, lane));
                ldsm4(bL[0], bfrag_addr(sbase + OFF_W1L, 128, nbse, L0, lane));
                ldsm4(bL[1], bfrag_addr(sbase + OFF_W1L, 128, nbse + 16, L0, lane));
#pragma unroll
                for (int mt = 0; mt < 2; ++mt)
#pragma unroll
                    for (int nt = 0; nt < 4; ++nt) {
                        const uint* bh = &bH[nt >> 1][(nt & 1) * 2];
                        const uint* bl = &bL[nt >> 1][(nt & 1) * 2];
                        mma_bf16(dE[mt][nt], aH[mt], bh);
                        mma_bf16(dE[mt][nt], aH[mt], bl);
                        mma_bf16(dE[mt][nt], aL[mt], bh);
                    }
            }
#pragma unroll
            for (int mt = 0; mt < 2; ++mt) {
                int cA = c0 + mt * 16 + (lane >> 2);
                int cB = cA + 8;
#pragma unroll
                for (int nt = 0; nt < 4; ++nt) {
                    int rl = r0w + nt * 8 + (lane & 3) * 2;
                    int rg = ph * 128 + rl;
                    float b0v = sb1[rg], b1v = sb1[rg + 1];
                    float v0 = fmaxf(dE[mt][nt][0] + b0v, 0.f);
                    float v1 = fmaxf(dE[mt][nt][1] + b1v, 0.f);
                    float v2 = fmaxf(dE[mt][nt][2] + b0v, 0.f);
                    float v3 = fmaxf(dE[mt][nt][3] + b1v, 0.f);
                    int lA = (rl * 2) ^ ((cA & 7) << 4);
                    int lB = (rl * 2) ^ ((cB & 7) << 4);
                    *(uint*)(smem + OFF_HH + cA * 256 + lA) = bf2(v0, v1);
                    *(uint*)(smem + OFF_HL + cA * 256 + lA) = bf2(bfres(v0), bfres(v1));
                    *(uint*)(smem + OFF_HH + cB * 256 + lB) = bf2(v2, v3);
                    *(uint*)(smem + OFF_HL + cB * 256 + lB) = bf2(bfres(v2), bfres(v3));
                }
            }
            __syncthreads();

#pragma unroll
            for (int ks = 0; ks < 8; ++ks) {
                int L0 = ks * 32;
                int L0w = ph * 256 + L0;
                uint aH[2][4], aL[2][4], bH[4], bL[4];
                ldsm4(aH[0], afrag_addr(sbase + OFF_HH, 256, c0, L0, lane));
                ldsm4(aH[1], afrag_addr(sbase + OFF_HH, 256, c0 + 16, L0, lane));
                ldsm4(aL[0], afrag_addr(sbase + OFF_HL, 256, c0, L0, lane));
                ldsm4(aL[1], afrag_addr(sbase + OFF_HL, 256, c0 + 16, L0, lane));
                ldsm4(bH, bfrag_addr(sbase + OFF_W2H, 512, o0, L0w, lane));
                ldsm4(bL, bfrag_addr(sbase + OFF_W2L, 512, o0, L0w, lane));
#pragma unroll
                for (int mt = 0; mt < 2; ++mt)
#pragma unroll
                    for (int nt = 0; nt < 2; ++nt) {
                        const uint* bh = &bH[nt * 2];
                        const uint* bl = &bL[nt * 2];
                        mma_bf16(dF[mt][nt], aH[mt], bh);
                        mma_bf16(dF[mt][nt], aH[mt], bl);
                        mma_bf16(dF[mt][nt], aL[mt], bh);
                    }
            }
            __syncthreads();
        }

        {
            float* simf = (float*)(smem + OFF_SIM);
#pragma unroll
            for (int mt = 0; mt < 2; ++mt) {
                int cA = c0 + mt * 16 + (lane >> 2);
                int cB = cA + 8;
#pragma unroll
                for (int nt = 0; nt < 2; ++nt) {
                    int o = o0 + nt * 8 + (lane & 3) * 2;
                    float b0v = sb2[o], b1v = sb2[o + 1];
                    simf[cA * 68 + o]     = dF[mt][nt][0] + b0v;
                    simf[cA * 68 + o + 1] = dF[mt][nt][1] + b1v;
                    simf[cB * 68 + o]     = dF[mt][nt][2] + b0v;
                    simf[cB * 68 + o + 1] = dF[mt][nt][3] + b1v;
                }
            }
        }
        __syncthreads();

        {
            int o = t >> 3, q = t & 7;
            const float* sp = (const float*)(smem + OFF_SIM) + (q * 16) * 68 + o;
            float mx = -3.4e38f;
#pragma unroll
            for (int k = 0; k < 16; ++k) mx = fmaxf(mx, sp[k * 68]);
            float vg[16];
#pragma unroll
            for (int k = 0; k < 16; ++k) {
                int j = sj[q * 16 + k];
                vg[k] = __ldg(g_qkv + ((size_t)(b * NN + j)) * 192 + 128 + o)
                      + __ldg(g_pe + ((size_t)b * 65536 + (size_t)n0 * 16 + q * 16 + k) * 64 + o);
            }
            float s = 0.f, a = 0.f;
#pragma unroll
            for (int k = 0; k < 16; ++k) {
                float e = __expf(sp[k * 68] - mx);
                s += e;
                a = fmaf(e, vg[k], a);
            }
            out[((size_t)(b * 64 + o)) * NN + n0 + q] = a / s;
        }
    }
}

// ---------------------------------------------------------------------------
extern "C" void kernel_launch(void* const* d_in, const int* in_sizes, int n_in,
                              void* d_out, int out_size) {
    (void)in_sizes; (void)n_in; (void)out_size;
    const float* xyz    = (const float*)d_in[0];
    const float* points = (const float*)d_in[1];
    const float* w_qkv  = (const float*)d_in[2];
    const float* w_pos1 = (const float*)d_in[3];
    const float* b_pos1 = (const float*)d_in[4];
    const float* w_pos2 = (const float*)d_in[5];
    const float* b_pos2 = (const float*)d_in[6];
    const float* w_att1 = (const float*)d_in[7];
    const float* b_att1 = (const float*)d_in[8];
    const float* w_att2 = (const float*)d_in[9];
    const float* b_att2 = (const float*)d_in[10];
    float* out = (float*)d_out;

    cudaFuncSetAttribute(qkv_kernel, cudaFuncAttributeMaxDynamicSharedMemorySize, 49152);
    cudaFuncSetAttribute(knn_kernel, cudaFuncAttributeMaxDynamicSharedMemorySize, 98304);
    cudaFuncSetAttribute(pos_kernel, cudaFuncAttributeMaxDynamicSharedMemorySize, SMEM_POS);
    cudaFuncSetAttribute(fused_mma_kernel, cudaFuncAttributeMaxDynamicSharedMemorySize, SMEM_TC);

    qkv_kernel<<<BB * (NN / 64), 256, 49152>>>(points, w_qkv);
    knn_kernel<<<BB * (NN / 64), 256, 98304>>>(xyz);
    pos_kernel<<<BB * NN * KK / 256, 256, SMEM_POS>>>(xyz, w_pos1, b_pos1, w_pos2, b_pos2);
    fused_mma_kernel<<<BB * (NN / 16), 512, SMEM_TC>>>(w_att1, b_att1, w_att2, b_att2, out);
}